// round 13
// baseline (speedup 1.0000x reference)
#include <cuda_runtime.h>
#include <cuda_fp16.h>
#include <cstdint>

#define B_ 128
#define S_ 256
#define C_ 512
#define T_ 128
#define V_ 256
#define H_ 512
#define A_ 512
#define NG 2048   /* 4*H */
#define KX 1024   /* A + H */
#define NBLK 128

// smem layout
#define SM_A0 0
#define SM_A1 32768
#define SM_B0 65536
#define SM_B1 69632
#define SM_R_OFF 73728          /* 64KB partials */
#define SM_Q_OFF 139264
#define SM_VA_OFF 141312
#define SM_S_OFF 143360
#define SM_RED_OFF 144384
#define SM_REDB_OFF 144512
#define SM_WCAT_OFF 144640      /* 32KB resident Wcat slice (8 tiles of 4KB) */
#define SM_KC_OFF 177408
#define NC 52                   /* cached kproj rows per block */
#define KP 72                   /* keys rows prefetched into A0.. during PB */
#define SMEM_DYN (SM_KC_OFF + NC*1024)   /* 230656 */

// ---------------- device scratch ----------------
__device__ __half g_feats16[B_*S_*C_];
__device__ __half g_keys16 [B_*S_*A_];
__device__ __half g_kproj16[B_*S_*A_];
__device__ __half g_Icw16  [A_*C_];
__device__ __half g_Wk16   [A_*A_];
__device__ __half g_Wcomb16[A_*H_];   // (Wq @ Hc_w) fp16
__device__ float  g_bqc    [A_];      // bq + Wq @ Hc_b
__device__ __half g_Wcat16 [NG*KX];   // interleaved-gate [W_ih[:,V:] | W_hh] fp16
__device__ float  g_bcombIl[NG];
__device__ float  g_WihVTil[V_*NG];
__device__ __half g_Wout16 [V_*H_];
__device__ __half g_h16    [B_*H_];
__device__ float  g_c      [B_*H_];
__device__ __half g_Xh     [B_*KX];   // [ctx | h] fp16
__device__ float  g_qw     [B_*A_];
__device__ unsigned g_sync;
__device__ unsigned g_syncA;   // PB ctx-ready arrivals
__device__ unsigned g_syncB;   // PC h-half-consumed arrivals

// ---------------- helpers ----------------
__device__ __forceinline__ float wsum(float v) {
    #pragma unroll
    for (int o = 16; o > 0; o >>= 1) v += __shfl_down_sync(0xffffffffu, v, o);
    return v;
}
__device__ __forceinline__ float wmax(float v) {
    #pragma unroll
    for (int o = 16; o > 0; o >>= 1) v = fmaxf(v, __shfl_down_sync(0xffffffffu, v, o));
    return v;
}
__device__ __forceinline__ float sigm(float x) { return 1.f / (1.f + expf(-x)); }
__device__ __forceinline__ __half2 ath_tanh_h2(__half2 x) {
    __half2 y;
    asm("tanh.approx.f16x2 %0, %1;"
        : "=r"(*(uint32_t*)&y) : "r"(*(uint32_t*)&x));
    return y;
}
__device__ __forceinline__ void ldmx4(uint32_t* r, uint32_t addr) {
    asm volatile("ldmatrix.sync.aligned.m8n8.x4.shared.b16 {%0,%1,%2,%3}, [%4];"
        : "=r"(r[0]), "=r"(r[1]), "=r"(r[2]), "=r"(r[3]) : "r"(addr));
}
__device__ __forceinline__ void ldmx2(uint32_t &r0, uint32_t &r1, uint32_t addr) {
    asm volatile("ldmatrix.sync.aligned.m8n8.x2.shared.b16 {%0,%1}, [%2];"
        : "=r"(r0), "=r"(r1) : "r"(addr));
}
__device__ __forceinline__ void mma16816(float* c, const uint32_t* a, uint32_t b0, uint32_t b1) {
    asm volatile("mma.sync.aligned.m16n8k16.row.col.f32.f16.f16.f32 "
        "{%0,%1,%2,%3}, {%4,%5,%6,%7}, {%8,%9}, {%0,%1,%2,%3};"
        : "+f"(c[0]), "+f"(c[1]), "+f"(c[2]), "+f"(c[3])
        : "r"(a[0]), "r"(a[1]), "r"(a[2]), "r"(a[3]), "r"(b0), "r"(b1));
}
__device__ __forceinline__ void cpasync16(uint32_t saddr, const void* gaddr) {
    asm volatile("cp.async.cg.shared.global [%0], [%1], 16;"
                 :: "r"(saddr), "l"(gaddr) : "memory");
}
#define CP_COMMIT() asm volatile("cp.async.commit_group;" ::: "memory")
#define CP_WAIT(n)  asm volatile("cp.async.wait_group %0;" :: "n"(n) : "memory")
__device__ __forceinline__ void arrive_rel(unsigned* ctr) {
    asm volatile("red.release.gpu.global.add.u32 [%0], 1;" :: "l"(ctr) : "memory");
}
__device__ __forceinline__ void poll_acq(unsigned* ctr, unsigned tgt) {
    unsigned v;
    do {
        asm volatile("ld.acquire.gpu.global.u32 %0, [%1];" : "=r"(v) : "l"(ctr) : "memory");
    } while (v < tgt);
}

// -------- 64x64 mma tile (8 warps / 256 threads), Ch = A@B^T + bias --------
__device__ void mma_tile64(const __half* __restrict__ Ag, const __half* __restrict__ Bg,
                           const float* __restrict__ bias, __half* __restrict__ Ch,
                           int K, int ldc, int m0, int n0, int stid,
                           char* sA, char* sB)
{
    const int lane = stid & 31, wid8 = stid >> 5;
    const int mg = wid8 >> 2, ng = wid8 & 3;
    uint32_t sa = (uint32_t)__cvta_generic_to_shared(sA);
    uint32_t sbp = (uint32_t)__cvta_generic_to_shared(sB);

    float cfr[2][2][4];
    #pragma unroll
    for (int i = 0; i < 2; i++)
        #pragma unroll
        for (int j = 0; j < 2; j++)
            #pragma unroll
            for (int q = 0; q < 4; q++) cfr[i][j][q] = 0.f;

    for (int kc = 0; kc < K / 64; kc++) {
        __syncthreads();
        #pragma unroll
        for (int r = 0; r < 2; r++) {
            int idx = stid + r * 256;
            int row = idx >> 3, ch = idx & 7;
            int chs = ch ^ (row & 7);
            *(uint4*)(sA + row * 128 + chs * 16) =
                *(const uint4*)(Ag + (size_t)(m0 + row) * K + kc * 64 + ch * 8);
            *(uint4*)(sB + row * 128 + chs * 16) =
                *(const uint4*)(Bg + (size_t)(n0 + row) * K + kc * 64 + ch * 8);
        }
        __syncthreads();
        #pragma unroll
        for (int s = 0; s < 4; s++) {
            uint32_t a0[4], a1[4], bb[4];
            int row = mg * 32 + (lane & 15);
            int ch = (s * 2 + (lane >> 4)) ^ (row & 7);
            ldmx4(a0, sa + row * 128 + ch * 16);
            row += 16; ch = (s * 2 + (lane >> 4)) ^ (row & 7);
            ldmx4(a1, sa + row * 128 + ch * 16);
            int n = ng * 16 + ((lane >> 4) << 3) + (lane & 7);
            ch = (s * 2 + ((lane >> 3) & 1)) ^ (n & 7);
            ldmx4(bb, sbp + n * 128 + ch * 16);
            mma16816(cfr[0][0], a0, bb[0], bb[1]);
            mma16816(cfr[0][1], a0, bb[2], bb[3]);
            mma16816(cfr[1][0], a1, bb[0], bb[1]);
            mma16816(cfr[1][1], a1, bb[2], bb[3]);
        }
    }
    int g = lane >> 2, t = lane & 3;
    #pragma unroll
    for (int mf = 0; mf < 2; mf++)
        #pragma unroll
        for (int nf = 0; nf < 2; nf++) {
            int row = m0 + mg * 32 + mf * 16 + g;
            int col = n0 + ng * 16 + nf * 8 + 2 * t;
            float b0v = bias ? bias[col] : 0.f, b1v = bias ? bias[col + 1] : 0.f;
            float* c = cfr[mf][nf];
            *(__half2*)(Ch + (size_t)row * ldc + col) =
                __floats2half2_rn(c[0] + b0v, c[1] + b1v);
            *(__half2*)(Ch + (size_t)(row + 8) * ldc + col) =
                __floats2half2_rn(c[2] + b0v, c[3] + b1v);
        }
}

__global__ void mma_pre(const __half* __restrict__ Ag, const __half* __restrict__ Bg,
                        const float* __restrict__ bias, __half* __restrict__ Ch,
                        int K, int ldc)
{
    __shared__ __align__(16) char sA[8192];
    __shared__ __align__(16) char sB[8192];
    mma_tile64(Ag, Bg, bias, Ch, K, ldc, blockIdx.y * 64, blockIdx.x * 64,
               threadIdx.x, sA, sB);
}

// -------- NN GEMM for Wcomb: C[a][k] = sum_m Wq[a][m] * Hc_w[m][k], fp16 out --
__global__ void gemm_wcomb_nn(const float* __restrict__ Wq, const float* __restrict__ Hcw,
                              __half* __restrict__ Ch)
{
    __shared__ __align__(16) float As[16][68];
    __shared__ __align__(16) float Bs[16][68];
    const int tid = threadIdx.x;
    const int tx = tid & 15, ty = tid >> 4;
    const int n0 = blockIdx.x * 64, m0 = blockIdx.y * 64;
    float acc[4][4];
    #pragma unroll
    for (int i = 0; i < 4; i++)
        #pragma unroll
        for (int j = 0; j < 4; j++) acc[i][j] = 0.f;
    const int lr = tid >> 2, lc = (tid & 3) * 4;
    const int br = tid >> 4, bc = (tid & 15) * 4;
    for (int kb = 0; kb < A_; kb += 16) {
        float4 av = *(const float4*)(Wq + (size_t)(m0 + lr) * A_ + kb + lc);
        As[lc+0][lr] = av.x; As[lc+1][lr] = av.y; As[lc+2][lr] = av.z; As[lc+3][lr] = av.w;
        float4 bv = *(const float4*)(Hcw + (size_t)(kb + br) * H_ + n0 + bc);
        Bs[br][bc+0] = bv.x; Bs[br][bc+1] = bv.y; Bs[br][bc+2] = bv.z; Bs[br][bc+3] = bv.w;
        __syncthreads();
        #pragma unroll
        for (int kk = 0; kk < 16; kk++) {
            float4 a4 = *(const float4*)&As[kk][ty * 4];
            float4 b4 = *(const float4*)&Bs[kk][tx * 4];
            float a_[4] = {a4.x, a4.y, a4.z, a4.w};
            float b_[4] = {b4.x, b4.y, b4.z, b4.w};
            #pragma unroll
            for (int i = 0; i < 4; i++)
                #pragma unroll
                for (int j = 0; j < 4; j++) acc[i][j] = fmaf(a_[i], b_[j], acc[i][j]);
        }
        __syncthreads();
    }
    #pragma unroll
    for (int i = 0; i < 4; i++)
        #pragma unroll
        for (int j = 0; j < 4; j++)
            Ch[(size_t)(m0 + ty * 4 + i) * H_ + n0 + tx * 4 + j] = __float2half(acc[i][j]);
}

// ---------------- fused one-time prep (single launch) ----------------
__global__ void k_prep_all(const float* __restrict__ feats, const float* __restrict__ Ic_w,
                           const float* __restrict__ Wk, const float* __restrict__ Wout,
                           const float* __restrict__ W_ih, const float* __restrict__ W_hh,
                           const float* __restrict__ b_ih, const float* __restrict__ b_hh,
                           const float* __restrict__ Wq, const float* __restrict__ bq,
                           const float* __restrict__ Hcb)
{
    long idx = (long)blockIdx.x * 256 + threadIdx.x;
    if (idx < (long)B_*S_*C_) g_feats16[idx] = __float2half(feats[idx]);
    if (idx < A_*C_)  g_Icw16[idx]  = __float2half(Ic_w[idx]);
    if (idx < A_*A_)  g_Wk16[idx]   = __float2half(Wk[idx]);
    if (idx < V_*H_)  g_Wout16[idx] = __float2half(Wout[idx]);
    if (idx < (long)NG*KX) {
        int nil = (int)(idx >> 10), k = (int)(idx & 1023);
        int n = (nil & 3) * H_ + (nil >> 2);
        float v = (k < A_) ? W_ih[(size_t)n * (V_ + A_) + V_ + k]
                           : W_hh[(size_t)n * H_ + (k - A_)];
        g_Wcat16[idx] = __float2half(v);
    }
    if (idx < (long)V_*NG) {
        int v = (int)(idx >> 11), nil = (int)(idx & 2047);
        int n = (nil & 3) * H_ + (nil >> 2);
        g_WihVTil[idx] = W_ih[(size_t)n * (V_ + A_) + v];
    }
    if (idx < B_*H_) {
        g_h16[idx] = __float2half(0.f);
        g_c[idx] = 0.f;
        int b = (int)(idx >> 9), j = (int)(idx & 511);
        g_Xh[b * KX + A_ + j] = __float2half(0.f);
    }
    if (idx < NG) {
        int nn = ((int)idx & 3) * H_ + ((int)idx >> 2);
        g_bcombIl[idx] = b_ih[nn] + b_hh[nn];
    }
    if (idx < A_) {
        float s = bq[idx];
        for (int m = 0; m < A_; m++) s += Wq[idx * A_ + m] * Hcb[m];
        g_bqc[idx] = s;
    }
    if (idx == 0) { g_sync = 0u; g_syncA = 0u; g_syncB = 0u; }
}

// ---------------- single-counter grid sync ----------------
__device__ __forceinline__ void gridsync(unsigned &sc) {
    __syncthreads();
    sc += NBLK;
    if (threadIdx.x == 0) {
        arrive_rel(&g_sync);
        poll_acq(&g_sync, sc);
    }
    __syncthreads();
}

// mma GEMM (double-buffered cp.async): partials for C[128, n0..n0+8) into smem
__device__ __forceinline__ void mma_gemm_n8(const __half* __restrict__ Ag, int lda,
        const __half* __restrict__ Bg, int ldb, int n0, int K,
        char* dyn, uint32_t sb)
{
    const int tid = threadIdx.x, lane = tid & 31, wid = tid >> 5;
    const int mg = wid >> 3, kg = wid & 7;
    float cfr[2][4];
    #pragma unroll
    for (int i = 0; i < 2; i++)
        #pragma unroll
        for (int q = 0; q < 4; q++) cfr[i][q] = 0.f;

    const int nkc = K / 128;

    // prefetch stage 0
    {
        #pragma unroll
        for (int r = 0; r < 2; r++) {
            int idx = tid + r * 1024;
            int row = idx >> 4, ch = idx & 15, chs = ch ^ (row & 7);
            cpasync16(sb + SM_A0 + row * 256 + chs * 16,
                      Ag + (size_t)row * lda + ch * 8);
        }
        if (tid < 128) {
            int row = tid >> 4, ch = tid & 15, chs = ch ^ (row & 7);
            cpasync16(sb + SM_B0 + row * 256 + chs * 16,
                      Bg + (size_t)(n0 + row) * ldb + ch * 8);
        }
        CP_COMMIT();
    }

    for (int kc = 0; kc < nkc; kc++) {
        if (kc + 1 < nkc) {
            int buf = (kc + 1) & 1;
            #pragma unroll
            for (int r = 0; r < 2; r++) {
                int idx = tid + r * 1024;
                int row = idx >> 4, ch = idx & 15, chs = ch ^ (row & 7);
                cpasync16(sb + (buf ? SM_A1 : SM_A0) + row * 256 + chs * 16,
                          Ag + (size_t)row * lda + (kc + 1) * 128 + ch * 8);
            }
            if (tid < 128) {
                int row = tid >> 4, ch = tid & 15, chs = ch ^ (row & 7);
                cpasync16(sb + (buf ? SM_B1 : SM_B0) + row * 256 + chs * 16,
                          Bg + (size_t)(n0 + row) * ldb + (kc + 1) * 128 + ch * 8);
            }
            CP_COMMIT();
            CP_WAIT(1);
        } else {
            CP_WAIT(0);
        }
        __syncthreads();
        uint32_t abase = sb + ((kc & 1) ? SM_A1 : SM_A0);
        uint32_t bbase = sb + ((kc & 1) ? SM_B1 : SM_B0);
        uint32_t a0[4], a1[4], b0, b1;
        int s = kg;
        int row = mg * 32 + (lane & 15);
        int ch = (s * 2 + (lane >> 4)) ^ (row & 7);
        ldmx4(a0, abase + row * 256 + ch * 16);
        row += 16; ch = (s * 2 + (lane >> 4)) ^ (row & 7);
        ldmx4(a1, abase + row * 256 + ch * 16);
        int n = lane & 7;
        ch = (s * 2 + ((lane >> 3) & 1)) ^ (n & 7);
        ldmx2(b0, b1, bbase + n * 256 + ch * 16);
        mma16816(cfr[0], a0, b0, b1);
        mma16816(cfr[1], a1, b0, b1);
        __syncthreads();
    }
    float* buf = (float*)(dyn + SM_R_OFF) + kg * (128 * 8);
    int g = lane >> 2, t = lane & 3;
    #pragma unroll
    for (int mf = 0; mf < 2; mf++) {
        int r0 = mg * 32 + mf * 16 + g;
        *(float2*)(buf + r0 * 8 + 2 * t) = make_float2(cfr[mf][0], cfr[mf][1]);
        *(float2*)(buf + (r0 + 8) * 8 + 2 * t) = make_float2(cfr[mf][2], cfr[mf][3]);
    }
    __syncthreads();
}

__global__ void __launch_bounds__(1024, 1) persist(
        const int* __restrict__ labels, const float* __restrict__ va,
        const float* __restrict__ bk, const float* __restrict__ bout,
        float* __restrict__ out)
{
    extern __shared__ __align__(16) char dyn[];
    const uint32_t sb = (uint32_t)__cvta_generic_to_shared(dyn);
    float* sRbuf = (float*)(dyn + SM_R_OFF);
    float* sQ    = (float*)(dyn + SM_Q_OFF);
    float* sVa   = (float*)(dyn + SM_VA_OFF);
    float* sS    = (float*)(dyn + SM_S_OFF);
    float* sRed  = (float*)(dyn + SM_RED_OFF);
    float* sRedB = (float*)(dyn + SM_REDB_OFF);

    const int bid = blockIdx.x, tid = threadIdx.x;
    const int lane = tid & 31, wp = tid >> 5;
    unsigned sc = 0;

    // ==== prologue: kproj = keys @ Wk^T + bk (4096 tiles, 4 sub-jobs/block) ====
    {
        int sg = tid >> 8, stid = tid & 255;
        char* sA = dyn + sg * 16384;
        char* sB = sA + 8192;
        #pragma unroll 1
        for (int it = 0; it < 8; it++) {
            int job = bid * 32 + sg * 8 + it;
            int m0 = (job >> 3) * 64, n0 = (job & 7) * 64;
            mma_tile64(g_keys16, g_Wk16, bk, g_kproj16, A_, A_, m0, n0, stid, sA, sB);
        }
    }
    gridsync(sc);
    // load this block's kproj cache (rows 0..NC-1 of batch bid)
    {
        const uint4* src = (const uint4*)(g_kproj16 + (size_t)bid * S_ * A_);
        uint4* dst = (uint4*)(dyn + SM_KC_OFF);
        #pragma unroll 1
        for (int i = tid; i < NC * 64; i += 1024) dst[i] = src[i];
    }
    // load this block's Wcat slice (16 rows x 1024) into resident smem, per-kc tiles
    {
        int n0 = bid * 16;
        #pragma unroll
        for (int r = 0; r < 2; r++) {
            int idx = tid + r * 1024;               // 0..2047
            int kc = idx >> 8, rem = idx & 255;
            int row = rem >> 4, ch = rem & 15;
            int chs = ch ^ (row & 7);
            *(uint4*)(dyn + SM_WCAT_OFF + kc * 4096 + row * 256 + chs * 16) =
                *(const uint4*)(g_Wcat16 + (size_t)(n0 + row) * KX + kc * 128 + ch * 8);
        }
    }
    __syncthreads();

    for (int t = 0; t < T_; t++) {
        const unsigned tgt = (unsigned)(t + 1) * NBLK;
        // ==== PA: qw (blocks 0-63, n-tile 8), out[t-1] (blocks 64-95, n-tile 8)
        if (bid < 64) {
            int n0 = bid * 8;
            mma_gemm_n8(g_h16, H_, g_Wcomb16, H_, n0, H_, dyn, sb);
            int b = tid >> 3, nl = tid & 7;
            float s = g_bqc[n0 + nl];
            #pragma unroll
            for (int kg = 0; kg < 8; kg++) s += sRbuf[kg * 1024 + b * 8 + nl];
            g_qw[b * A_ + n0 + nl] = s;
        } else if (bid < 96 && t > 0) {
            int n0 = (bid - 64) * 8;
            mma_gemm_n8(g_h16, H_, g_Wout16, H_, n0, H_, dyn, sb);
            int b = tid >> 3, nl = tid & 7;
            float s = bout[n0 + nl];
            #pragma unroll
            for (int kg = 0; kg < 8; kg++) s += sRbuf[kg * 1024 + b * 8 + nl];
            out[((size_t)b * T_ + (t - 1)) * V_ + n0 + nl] = s;
        }
        gridsync(sc);

        // ==== PB: attention for batch b = bid ====
        {
            const int b = bid;
            // prefetch first KP keys rows into the (idle) GEMM staging region
            {
                const __half* kbase = g_keys16 + (size_t)b * S_ * A_;
                #pragma unroll
                for (int r = 0; r < 5; r++) {
                    int idx = tid + r * 1024;       // KP*64 = 4608 chunks
                    if (idx < KP * 64) {
                        int row = idx >> 6, cg = idx & 63;
                        cpasync16(sb + row * 1024 + cg * 16,
                                  kbase + (size_t)row * A_ + cg * 8);
                    }
                }
                CP_COMMIT();
            }
            if (tid < A_) { sQ[tid] = g_qw[b * A_ + tid]; sVa[tid] = va[tid]; }
            __syncthreads();

            __half2 q2[8], v2[8];
            {
                const float4* q4 = (const float4*)(sQ + lane * 16);
                const float4* v4 = (const float4*)(sVa + lane * 16);
                #pragma unroll
                for (int i = 0; i < 4; i++) {
                    float4 qv = q4[i], vv = v4[i];
                    q2[2*i]   = __floats2half2_rn(qv.x, qv.y);
                    q2[2*i+1] = __floats2half2_rn(qv.z, qv.w);
                    v2[2*i]   = __floats2half2_rn(vv.x, vv.y);
                    v2[2*i+1] = __floats2half2_rn(vv.z, vv.w);
                }
            }
            #pragma unroll 2
            for (int r = 0; r < 8; r++) {
                int j = wp * 8 + r;
                const uint4* rowp = (j < NC)
                    ? (const uint4*)(dyn + SM_KC_OFF + j * 1024)
                    : (const uint4*)(g_kproj16 + ((size_t)b * S_ + j) * A_);
                uint4 d0 = rowp[lane * 2];
                uint4 d1 = rowp[lane * 2 + 1];
                const __half2* h0 = (const __half2*)&d0;
                const __half2* h1 = (const __half2*)&d1;
                float acc = 0.f;
                #pragma unroll
                for (int i = 0; i < 4; i++) {
                    __half2 p0 = __hmul2(v2[i],     ath_tanh_h2(__hadd2(h0[i], q2[i])));
                    __half2 p1 = __hmul2(v2[4 + i], ath_tanh_h2(__hadd2(h1[i], q2[4 + i])));
                    float2 f0 = __half22float2(p0);
                    float2 f1 = __half22float2(p1);
                    acc += (f0.x + f0.y) + (f1.x + f1.y);
                }
                acc = wsum(acc);
                if (lane == 0) sS[j] = acc;
            }
            __syncthreads();

            float v = 0.f, e = 0.f;
            if (tid < 256) {
                v = sS[tid];
                float m = wmax(v);
                if (lane == 0) sRed[wp] = m;
            }
            __syncthreads();
            if (tid < 256) {
                float m = sRed[0];
                #pragma unroll
                for (int i = 1; i < 8; i++) m = fmaxf(m, sRed[i]);
                e = expf(v - m);
                float s = wsum(e);
                if (lane == 0) sRedB[wp] = s;
            }
            __syncthreads();
            if (tid < 256) {
                float s = sRedB[0];
                #pragma unroll
                for (int i = 1; i < 8; i++) s += sRedB[i];
                sS[tid] = e / s;
            }
            CP_WAIT(0);
            __syncthreads();

            // context: wide uint4 loads; rows < KP come from smem prefetch
            {
                int cg = tid & 63, rg = tid >> 6;
                const uint4* kb4 = (const uint4*)(g_keys16 + (size_t)b * S_ * A_) + cg;
                float facc[8];
                #pragma unroll
                for (int i = 0; i < 8; i++) facc[i] = 0.f;
                #pragma unroll
                for (int r = 0; r < 16; r++) {
                    int j = rg * 16 + r;
                    uint4 kv = (j < KP)
                        ? *(const uint4*)(dyn + j * 1024 + cg * 16)
                        : kb4[(size_t)j * 64];
                    float w = sS[j];
                    const __half2* hh = (const __half2*)&kv;
                    #pragma unroll
                    for (int i = 0; i < 4; i++) {
                        float2 f = __half22float2(hh[i]);
                        facc[2*i]   = fmaf(w, f.x, facc[2*i]);
                        facc[2*i+1] = fmaf(w, f.y, facc[2*i+1]);
                    }
                }
                float* dst = sRbuf + rg * 512 + cg * 8;
                *(float4*)(dst)     = make_float4(facc[0], facc[1], facc[2], facc[3]);
                *(float4*)(dst + 4) = make_float4(facc[4], facc[5], facc[6], facc[7]);
            }
            __syncthreads();
            if (tid < 256) {
                int a0 = tid * 2;
                float sx = 0.f, sy = 0.f;
                #pragma unroll
                for (int rg2 = 0; rg2 < 16; rg2++) {
                    float2 p = *(const float2*)(sRbuf + rg2 * 512 + a0);
                    sx += p.x; sy += p.y;
                }
                ((__half2*)(g_Xh + (size_t)b * KX))[tid] =
                    __floats2half2_rn(sx, sy);
            }
            __syncthreads();
            if (tid == 0) arrive_rel(&g_syncA);   // ctx for batch bid published
        }
        // NOTE: no gridsync here — PC h-half proceeds immediately

        // ==== PC: gates slice n0 = bid*16, K=1024; h-half first, then ctx-half
        {
            const int n0 = bid * 16;
            const int mg = wp >> 3, kg = wp & 7;
            float cfr[2][2][4];
            #pragma unroll
            for (int i = 0; i < 2; i++)
                #pragma unroll
                for (int j = 0; j < 2; j++)
                    #pragma unroll
                    for (int q = 0; q < 4; q++) cfr[i][j][q] = 0.f;

            const int kcs[8] = {4, 5, 6, 7, 0, 1, 2, 3};
            // prefetch A tile for kcs[0]=4 into buffer 0
            {
                #pragma unroll
                for (int r = 0; r < 2; r++) {
                    int idx = tid + r * 1024;
                    int row = idx >> 4, ch = idx & 15, chs = ch ^ (row & 7);
                    cpasync16(sb + SM_A0 + row * 256 + chs * 16,
                              g_Xh + (size_t)row * KX + 4 * 128 + ch * 8);
                }
                CP_COMMIT();
            }

            #pragma unroll 1
            for (int i = 0; i < 8; i++) {
                if (i + 1 < 8) {
                    if (i == 3) {
                        // all h tiles in flight/consumed; wait for everyone's ctx
                        if (tid == 0) poll_acq(&g_syncA, tgt);
                        __syncthreads();
                    }
                    int kcn = kcs[i + 1];
                    int bufn = (i + 1) & 1;
                    #pragma unroll
                    for (int r = 0; r < 2; r++) {
                        int idx = tid + r * 1024;
                        int row = idx >> 4, ch = idx & 15, chs = ch ^ (row & 7);
                        cpasync16(sb + (bufn ? SM_A1 : SM_A0) + row * 256 + chs * 16,
                                  g_Xh + (size_t)row * KX + kcn * 128 + ch * 8);
                    }
                    CP_COMMIT();
                    CP_WAIT(1);
                } else {
                    CP_WAIT(0);
                }
                __syncthreads();
                int kc = kcs[i];
                uint32_t abase = sb + ((i & 1) ? SM_A1 : SM_A0);
                uint32_t bbase = sb + SM_WCAT_OFF + kc * 4096;   // resident Wcat tile
                uint32_t a0[4], a1[4], bb[4];
                int s = kg;
                int row = mg * 32 + (lane & 15);
                int ch = (s * 2 + (lane >> 4)) ^ (row & 7);
                ldmx4(a0, abase + row * 256 + ch * 16);
                row += 16; ch = (s * 2 + (lane >> 4)) ^ (row & 7);
                ldmx4(a1, abase + row * 256 + ch * 16);
                int n = ((lane >> 4) << 3) + (lane & 7);
                ch = (s * 2 + ((lane >> 3) & 1)) ^ (n & 7);
                ldmx4(bb, bbase + n * 256 + ch * 16);
                mma16816(cfr[0][0], a0, bb[0], bb[1]);
                mma16816(cfr[0][1], a0, bb[2], bb[3]);
                mma16816(cfr[1][0], a1, bb[0], bb[1]);
                mma16816(cfr[1][1], a1, bb[2], bb[3]);
                __syncthreads();
                if (i == 3 && tid == 0) arrive_rel(&g_syncB);  // h-half consumed
            }
            float* buf = sRbuf + kg * (128 * 16);
            int g = lane >> 2, tt = lane & 3;
            #pragma unroll
            for (int mf = 0; mf < 2; mf++)
                #pragma unroll
                for (int nf = 0; nf < 2; nf++) {
                    int r0 = mg * 32 + mf * 16 + g;
                    int cc = nf * 8 + 2 * tt;
                    float* c = cfr[mf][nf];
                    *(float2*)(buf + r0 * 16 + cc) = make_float2(c[0], c[1]);
                    *(float2*)(buf + (r0 + 8) * 16 + cc) = make_float2(c[2], c[3]);
                }
            __syncthreads();
            // before writing h(t): ensure every block consumed h(t-1) tiles
            if (tid == 0) poll_acq(&g_syncB, tgt);
            __syncthreads();
            if (tid < 512) {
                int b = tid >> 2, jl = tid & 3;
                float4 s0 = make_float4(0.f, 0.f, 0.f, 0.f);
                #pragma unroll
                for (int kg2 = 0; kg2 < 8; kg2++) {
                    float4 v4 = *(const float4*)(sRbuf + kg2 * 2048 + b * 16 + jl * 4);
                    s0.x += v4.x; s0.y += v4.y; s0.z += v4.z; s0.w += v4.w;
                }
                int n = n0 + jl * 4;
                int lbl = labels[b * T_ + (t > 0 ? t - 1 : 0)];
                float4 bc = *(const float4*)(g_bcombIl + n);
                float4 wv = *(const float4*)(g_WihVTil + (size_t)lbl * NG + n);
                s0.x += bc.x + wv.x; s0.y += bc.y + wv.y;
                s0.z += bc.z + wv.z; s0.w += bc.w + wv.w;
                int j = bid * 4 + jl;
                float c = g_c[b * H_ + j];
                float cn = sigm(s0.y) * c + sigm(s0.x) * tanhf(s0.z);
                float hn = sigm(s0.w) * tanhf(cn);
                g_c[b * H_ + j] = cn;
                __half hh = __float2half(hn);
                g_h16[b * H_ + j] = hh;
                g_Xh[(size_t)b * KX + A_ + j] = hh;
            }
        }
        gridsync(sc);
    }

    // final out row t = T-1
    if (bid >= 64 && bid < 96) {
        int n0 = (bid - 64) * 8;
        mma_gemm_n8(g_h16, H_, g_Wout16, H_, n0, H_, dyn, sb);
        int b = tid >> 3, nl = tid & 7;
        float s = bout[n0 + nl];
        #pragma unroll
        for (int kg = 0; kg < 8; kg++) s += sRbuf[kg * 1024 + b * 8 + nl];
        out[((size_t)b * T_ + (T_ - 1)) * V_ + n0 + nl] = s;
    }
}

// ---------------- host driver ----------------
extern "C" void kernel_launch(void* const* d_in, const int* in_sizes, int n_in,
                              void* d_out, int out_size) {
    (void)in_sizes; (void)n_in; (void)out_size;
    const float* feats = (const float*)d_in[0];
    const int*   labels= (const int*)  d_in[1];
    const float* Ic_w  = (const float*)d_in[2];
    const float* Ic_b  = (const float*)d_in[3];
    const float* Hc_w  = (const float*)d_in[4];
    const float* Hc_b  = (const float*)d_in[5];
    const float* Wq    = (const float*)d_in[6];
    const float* bq    = (const float*)d_in[7];
    const float* Wk    = (const float*)d_in[8];
    const float* bk    = (const float*)d_in[9];
    const float* va    = (const float*)d_in[10];
    const float* W_ih  = (const float*)d_in[11];
    const float* b_ih  = (const float*)d_in[12];
    const float* W_hh  = (const float*)d_in[13];
    const float* b_hh  = (const float*)d_in[14];
    const float* Wout  = (const float*)d_in[15];
    const float* bout  = (const float*)d_in[16];
    float* out = (float*)d_out;

    __half *p_feats16, *p_keys16, *p_Icw16, *p_Wcomb16;
    cudaGetSymbolAddress((void**)&p_feats16, g_feats16);
    cudaGetSymbolAddress((void**)&p_keys16,  g_keys16);
    cudaGetSymbolAddress((void**)&p_Icw16,   g_Icw16);
    cudaGetSymbolAddress((void**)&p_Wcomb16, g_Wcomb16);

    cudaFuncSetAttribute(persist, cudaFuncAttributeMaxDynamicSharedMemorySize, SMEM_DYN);

    // launch 1: all elementwise prep fused
    k_prep_all<<<(B_*S_*C_)/256, 256>>>(feats, Ic_w, Wk, Wout, W_ih, W_hh,
                                        b_ih, b_hh, Wq, bq, Hc_b);
    // launch 2: Wcomb = Wq @ Hc_w  (NN, fp32 in, fp16 out)
    gemm_wcomb_nn<<<dim3(H_/64, A_/64), 256>>>(Wq, Hc_w, p_Wcomb16);
    // launch 3: keys16 = feats @ Ic_w^T + Ic_b
    mma_pre<<<dim3(A_/64, (B_*S_)/64), 256>>>(p_feats16, p_Icw16, Ic_b, p_keys16, C_, A_);
    // launch 4: persistent decode (prologue computes kproj, then 128 steps)
    persist<<<NBLK, 1024, SMEM_DYN>>>(labels, va, bk, bout, out);
}

// round 14
// speedup vs baseline: 1.0942x; 1.0942x over previous
#include <cuda_runtime.h>
#include <cuda_fp16.h>
#include <cstdint>

#define B_ 128
#define S_ 256
#define C_ 512
#define T_ 128
#define V_ 256
#define H_ 512
#define A_ 512
#define NG 2048   /* 4*H */
#define KX 1024   /* A + H */
#define NBLK 128

// smem layout
#define SM_A0 0
#define SM_A1 32768
#define SM_B0 65536
#define SM_B1 69632
#define SM_R_OFF 73728          /* 64KB partials */
#define SM_Q_OFF 139264
#define SM_VA_OFF 141312
#define SM_S_OFF 143360
#define SM_RED_OFF 144384
#define SM_REDB_OFF 144512
#define SM_WCAT_OFF 144640      /* 32KB resident Wcat slice (8 tiles of 4KB) */
#define SM_KC_OFF 177408
#define NC 52                   /* cached kproj rows per block */
#define KP 72                   /* keys rows prefetched into A0.. during PB */
#define SMEM_DYN (SM_KC_OFF + NC*1024)   /* 230656 */

// ---------------- device scratch ----------------
__device__ __half g_feats16[B_*S_*C_];
__device__ __half g_keys16 [B_*S_*A_];
__device__ __half g_kproj16[B_*S_*A_];
__device__ __half g_Icw16  [A_*C_];
__device__ __half g_Wk16   [A_*A_];
__device__ __half g_Wcomb16[A_*H_];   // (Wq @ Hc_w) fp16
__device__ float  g_bqc    [A_];      // bq + Wq @ Hc_b
__device__ __half g_Wcat16 [NG*KX];   // interleaved-gate [W_ih[:,V:] | W_hh] fp16
__device__ float  g_bcombIl[NG];
__device__ float  g_WihVTil[V_*NG];
__device__ __half g_Wout16 [V_*H_];
__device__ __half g_h16    [B_*H_];
__device__ float  g_c      [B_*H_];
__device__ __half g_Xh     [B_*KX];   // [ctx | h] fp16
__device__ float  g_qw     [B_*A_];
__device__ unsigned g_sync;

// ---------------- helpers ----------------
__device__ __forceinline__ float wsum(float v) {
    #pragma unroll
    for (int o = 16; o > 0; o >>= 1) v += __shfl_down_sync(0xffffffffu, v, o);
    return v;
}
__device__ __forceinline__ float wmax(float v) {
    #pragma unroll
    for (int o = 16; o > 0; o >>= 1) v = fmaxf(v, __shfl_down_sync(0xffffffffu, v, o));
    return v;
}
__device__ __forceinline__ float sigm(float x) { return 1.f / (1.f + expf(-x)); }
__device__ __forceinline__ __half2 ath_tanh_h2(__half2 x) {
    __half2 y;
    asm("tanh.approx.f16x2 %0, %1;"
        : "=r"(*(uint32_t*)&y) : "r"(*(uint32_t*)&x));
    return y;
}
__device__ __forceinline__ void ldmx4(uint32_t* r, uint32_t addr) {
    asm volatile("ldmatrix.sync.aligned.m8n8.x4.shared.b16 {%0,%1,%2,%3}, [%4];"
        : "=r"(r[0]), "=r"(r[1]), "=r"(r[2]), "=r"(r[3]) : "r"(addr));
}
__device__ __forceinline__ void ldmx2(uint32_t &r0, uint32_t &r1, uint32_t addr) {
    asm volatile("ldmatrix.sync.aligned.m8n8.x2.shared.b16 {%0,%1}, [%2];"
        : "=r"(r0), "=r"(r1) : "r"(addr));
}
__device__ __forceinline__ void mma16816(float* c, const uint32_t* a, uint32_t b0, uint32_t b1) {
    asm volatile("mma.sync.aligned.m16n8k16.row.col.f32.f16.f16.f32 "
        "{%0,%1,%2,%3}, {%4,%5,%6,%7}, {%8,%9}, {%0,%1,%2,%3};"
        : "+f"(c[0]), "+f"(c[1]), "+f"(c[2]), "+f"(c[3])
        : "r"(a[0]), "r"(a[1]), "r"(a[2]), "r"(a[3]), "r"(b0), "r"(b1));
}
__device__ __forceinline__ void cpasync16(uint32_t saddr, const void* gaddr) {
    asm volatile("cp.async.cg.shared.global [%0], [%1], 16;"
                 :: "r"(saddr), "l"(gaddr) : "memory");
}
#define CP_COMMIT() asm volatile("cp.async.commit_group;" ::: "memory")
#define CP_WAIT(n)  asm volatile("cp.async.wait_group %0;" :: "n"(n) : "memory")

// -------- 64x64 mma tile (8 warps / 256 threads), Ch = A@B^T + bias --------
__device__ void mma_tile64(const __half* __restrict__ Ag, const __half* __restrict__ Bg,
                           const float* __restrict__ bias, __half* __restrict__ Ch,
                           int K, int ldc, int m0, int n0, int stid,
                           char* sA, char* sB)
{
    const int lane = stid & 31, wid8 = stid >> 5;
    const int mg = wid8 >> 2, ng = wid8 & 3;
    uint32_t sa = (uint32_t)__cvta_generic_to_shared(sA);
    uint32_t sbp = (uint32_t)__cvta_generic_to_shared(sB);

    float cfr[2][2][4];
    #pragma unroll
    for (int i = 0; i < 2; i++)
        #pragma unroll
        for (int j = 0; j < 2; j++)
            #pragma unroll
            for (int q = 0; q < 4; q++) cfr[i][j][q] = 0.f;

    for (int kc = 0; kc < K / 64; kc++) {
        __syncthreads();
        #pragma unroll
        for (int r = 0; r < 2; r++) {
            int idx = stid + r * 256;
            int row = idx >> 3, ch = idx & 7;
            int chs = ch ^ (row & 7);
            *(uint4*)(sA + row * 128 + chs * 16) =
                *(const uint4*)(Ag + (size_t)(m0 + row) * K + kc * 64 + ch * 8);
            *(uint4*)(sB + row * 128 + chs * 16) =
                *(const uint4*)(Bg + (size_t)(n0 + row) * K + kc * 64 + ch * 8);
        }
        __syncthreads();
        #pragma unroll
        for (int s = 0; s < 4; s++) {
            uint32_t a0[4], a1[4], bb[4];
            int row = mg * 32 + (lane & 15);
            int ch = (s * 2 + (lane >> 4)) ^ (row & 7);
            ldmx4(a0, sa + row * 128 + ch * 16);
            row += 16; ch = (s * 2 + (lane >> 4)) ^ (row & 7);
            ldmx4(a1, sa + row * 128 + ch * 16);
            int n = ng * 16 + ((lane >> 4) << 3) + (lane & 7);
            ch = (s * 2 + ((lane >> 3) & 1)) ^ (n & 7);
            ldmx4(bb, sbp + n * 128 + ch * 16);
            mma16816(cfr[0][0], a0, bb[0], bb[1]);
            mma16816(cfr[0][1], a0, bb[2], bb[3]);
            mma16816(cfr[1][0], a1, bb[0], bb[1]);
            mma16816(cfr[1][1], a1, bb[2], bb[3]);
        }
    }
    int g = lane >> 2, t = lane & 3;
    #pragma unroll
    for (int mf = 0; mf < 2; mf++)
        #pragma unroll
        for (int nf = 0; nf < 2; nf++) {
            int row = m0 + mg * 32 + mf * 16 + g;
            int col = n0 + ng * 16 + nf * 8 + 2 * t;
            float b0v = bias ? bias[col] : 0.f, b1v = bias ? bias[col + 1] : 0.f;
            float* c = cfr[mf][nf];
            *(__half2*)(Ch + (size_t)row * ldc + col) =
                __floats2half2_rn(c[0] + b0v, c[1] + b1v);
            *(__half2*)(Ch + (size_t)(row + 8) * ldc + col) =
                __floats2half2_rn(c[2] + b0v, c[3] + b1v);
        }
}

__global__ void mma_pre(const __half* __restrict__ Ag, const __half* __restrict__ Bg,
                        const float* __restrict__ bias, __half* __restrict__ Ch,
                        int K, int ldc)
{
    __shared__ __align__(16) char sA[8192];
    __shared__ __align__(16) char sB[8192];
    mma_tile64(Ag, Bg, bias, Ch, K, ldc, blockIdx.y * 64, blockIdx.x * 64,
               threadIdx.x, sA, sB);
}

// -------- NN GEMM for Wcomb: C[a][k] = sum_m Wq[a][m] * Hc_w[m][k], fp16 out --
__global__ void gemm_wcomb_nn(const float* __restrict__ Wq, const float* __restrict__ Hcw,
                              __half* __restrict__ Ch)
{
    __shared__ __align__(16) float As[16][68];
    __shared__ __align__(16) float Bs[16][68];
    const int tid = threadIdx.x;
    const int tx = tid & 15, ty = tid >> 4;
    const int n0 = blockIdx.x * 64, m0 = blockIdx.y * 64;
    float acc[4][4];
    #pragma unroll
    for (int i = 0; i < 4; i++)
        #pragma unroll
        for (int j = 0; j < 4; j++) acc[i][j] = 0.f;
    const int lr = tid >> 2, lc = (tid & 3) * 4;
    const int br = tid >> 4, bc = (tid & 15) * 4;
    for (int kb = 0; kb < A_; kb += 16) {
        float4 av = *(const float4*)(Wq + (size_t)(m0 + lr) * A_ + kb + lc);
        As[lc+0][lr] = av.x; As[lc+1][lr] = av.y; As[lc+2][lr] = av.z; As[lc+3][lr] = av.w;
        float4 bv = *(const float4*)(Hcw + (size_t)(kb + br) * H_ + n0 + bc);
        Bs[br][bc+0] = bv.x; Bs[br][bc+1] = bv.y; Bs[br][bc+2] = bv.z; Bs[br][bc+3] = bv.w;
        __syncthreads();
        #pragma unroll
        for (int kk = 0; kk < 16; kk++) {
            float4 a4 = *(const float4*)&As[kk][ty * 4];
            float4 b4 = *(const float4*)&Bs[kk][tx * 4];
            float a_[4] = {a4.x, a4.y, a4.z, a4.w};
            float b_[4] = {b4.x, b4.y, b4.z, b4.w};
            #pragma unroll
            for (int i = 0; i < 4; i++)
                #pragma unroll
                for (int j = 0; j < 4; j++) acc[i][j] = fmaf(a_[i], b_[j], acc[i][j]);
        }
        __syncthreads();
    }
    #pragma unroll
    for (int i = 0; i < 4; i++)
        #pragma unroll
        for (int j = 0; j < 4; j++)
            Ch[(size_t)(m0 + ty * 4 + i) * H_ + n0 + tx * 4 + j] = __float2half(acc[i][j]);
}

// ---------------- fused one-time prep (single launch) ----------------
__global__ void k_prep_all(const float* __restrict__ feats, const float* __restrict__ Ic_w,
                           const float* __restrict__ Wk, const float* __restrict__ Wout,
                           const float* __restrict__ W_ih, const float* __restrict__ W_hh,
                           const float* __restrict__ b_ih, const float* __restrict__ b_hh,
                           const float* __restrict__ Wq, const float* __restrict__ bq,
                           const float* __restrict__ Hcb)
{
    long idx = (long)blockIdx.x * 256 + threadIdx.x;
    if (idx < (long)B_*S_*C_) g_feats16[idx] = __float2half(feats[idx]);
    if (idx < A_*C_)  g_Icw16[idx]  = __float2half(Ic_w[idx]);
    if (idx < A_*A_)  g_Wk16[idx]   = __float2half(Wk[idx]);
    if (idx < V_*H_)  g_Wout16[idx] = __float2half(Wout[idx]);
    if (idx < (long)NG*KX) {
        int nil = (int)(idx >> 10), k = (int)(idx & 1023);
        int n = (nil & 3) * H_ + (nil >> 2);
        float v = (k < A_) ? W_ih[(size_t)n * (V_ + A_) + V_ + k]
                           : W_hh[(size_t)n * H_ + (k - A_)];
        g_Wcat16[idx] = __float2half(v);
    }
    if (idx < (long)V_*NG) {
        int v = (int)(idx >> 11), nil = (int)(idx & 2047);
        int n = (nil & 3) * H_ + (nil >> 2);
        g_WihVTil[idx] = W_ih[(size_t)n * (V_ + A_) + v];
    }
    if (idx < B_*H_) {
        g_h16[idx] = __float2half(0.f);
        g_c[idx] = 0.f;
        int b = (int)(idx >> 9), j = (int)(idx & 511);
        g_Xh[b * KX + A_ + j] = __float2half(0.f);
    }
    if (idx < NG) {
        int nn = ((int)idx & 3) * H_ + ((int)idx >> 2);
        g_bcombIl[idx] = b_ih[nn] + b_hh[nn];
    }
    if (idx < A_) {
        float s = bq[idx];
        for (int m = 0; m < A_; m++) s += Wq[idx * A_ + m] * Hcb[m];
        g_bqc[idx] = s;
    }
    if (idx == 0) g_sync = 0u;
}

// ---------------- single-counter grid sync ----------------
__device__ __forceinline__ void gridsync(unsigned &sc) {
    __syncthreads();
    sc += NBLK;
    if (threadIdx.x == 0) {
        asm volatile("red.release.gpu.global.add.u32 [%0], 1;" :: "l"(&g_sync) : "memory");
        unsigned v;
        do {
            asm volatile("ld.acquire.gpu.global.u32 %0, [%1];" : "=r"(v) : "l"(&g_sync) : "memory");
        } while (v < sc);
    }
    __syncthreads();
}

// mma GEMM (double-buffered cp.async): partials for C[128, n0..n0+8) into smem
__device__ __forceinline__ void mma_gemm_n8(const __half* __restrict__ Ag, int lda,
        const __half* __restrict__ Bg, int ldb, int n0, int K,
        char* dyn, uint32_t sb)
{
    const int tid = threadIdx.x, lane = tid & 31, wid = tid >> 5;
    const int mg = wid >> 3, kg = wid & 7;
    float cfr[2][4];
    #pragma unroll
    for (int i = 0; i < 2; i++)
        #pragma unroll
        for (int q = 0; q < 4; q++) cfr[i][q] = 0.f;

    const int nkc = K / 128;

    // prefetch stage 0
    {
        #pragma unroll
        for (int r = 0; r < 2; r++) {
            int idx = tid + r * 1024;
            int row = idx >> 4, ch = idx & 15, chs = ch ^ (row & 7);
            cpasync16(sb + SM_A0 + row * 256 + chs * 16,
                      Ag + (size_t)row * lda + ch * 8);
        }
        if (tid < 128) {
            int row = tid >> 4, ch = tid & 15, chs = ch ^ (row & 7);
            cpasync16(sb + SM_B0 + row * 256 + chs * 16,
                      Bg + (size_t)(n0 + row) * ldb + ch * 8);
        }
        CP_COMMIT();
    }

    for (int kc = 0; kc < nkc; kc++) {
        if (kc + 1 < nkc) {
            int buf = (kc + 1) & 1;
            #pragma unroll
            for (int r = 0; r < 2; r++) {
                int idx = tid + r * 1024;
                int row = idx >> 4, ch = idx & 15, chs = ch ^ (row & 7);
                cpasync16(sb + (buf ? SM_A1 : SM_A0) + row * 256 + chs * 16,
                          Ag + (size_t)row * lda + (kc + 1) * 128 + ch * 8);
            }
            if (tid < 128) {
                int row = tid >> 4, ch = tid & 15, chs = ch ^ (row & 7);
                cpasync16(sb + (buf ? SM_B1 : SM_B0) + row * 256 + chs * 16,
                          Bg + (size_t)(n0 + row) * ldb + (kc + 1) * 128 + ch * 8);
            }
            CP_COMMIT();
            CP_WAIT(1);
        } else {
            CP_WAIT(0);
        }
        __syncthreads();
        uint32_t abase = sb + ((kc & 1) ? SM_A1 : SM_A0);
        uint32_t bbase = sb + ((kc & 1) ? SM_B1 : SM_B0);
        uint32_t a0[4], a1[4], b0, b1;
        int s = kg;
        int row = mg * 32 + (lane & 15);
        int ch = (s * 2 + (lane >> 4)) ^ (row & 7);
        ldmx4(a0, abase + row * 256 + ch * 16);
        row += 16; ch = (s * 2 + (lane >> 4)) ^ (row & 7);
        ldmx4(a1, abase + row * 256 + ch * 16);
        int n = lane & 7;
        ch = (s * 2 + ((lane >> 3) & 1)) ^ (n & 7);
        ldmx2(b0, b1, bbase + n * 256 + ch * 16);
        mma16816(cfr[0], a0, b0, b1);
        mma16816(cfr[1], a1, b0, b1);
        __syncthreads();
    }
    float* buf = (float*)(dyn + SM_R_OFF) + kg * (128 * 8);
    int g = lane >> 2, t = lane & 3;
    #pragma unroll
    for (int mf = 0; mf < 2; mf++) {
        int r0 = mg * 32 + mf * 16 + g;
        *(float2*)(buf + r0 * 8 + 2 * t) = make_float2(cfr[mf][0], cfr[mf][1]);
        *(float2*)(buf + (r0 + 8) * 8 + 2 * t) = make_float2(cfr[mf][2], cfr[mf][3]);
    }
    __syncthreads();
}

__global__ void __launch_bounds__(1024, 1) persist(
        const int* __restrict__ labels, const float* __restrict__ va,
        const float* __restrict__ bk, const float* __restrict__ bout,
        float* __restrict__ out)
{
    extern __shared__ __align__(16) char dyn[];
    const uint32_t sb = (uint32_t)__cvta_generic_to_shared(dyn);
    float* sRbuf = (float*)(dyn + SM_R_OFF);
    float* sQ    = (float*)(dyn + SM_Q_OFF);
    float* sVa   = (float*)(dyn + SM_VA_OFF);
    float* sS    = (float*)(dyn + SM_S_OFF);
    float* sRed  = (float*)(dyn + SM_RED_OFF);
    float* sRedB = (float*)(dyn + SM_REDB_OFF);

    const int bid = blockIdx.x, tid = threadIdx.x;
    const int lane = tid & 31, wp = tid >> 5;
    unsigned sc = 0;

    // ==== prologue: kproj = keys @ Wk^T + bk (4096 tiles, 4 sub-jobs/block) ====
    {
        int sg = tid >> 8, stid = tid & 255;
        char* sA = dyn + sg * 16384;
        char* sB = sA + 8192;
        #pragma unroll 1
        for (int it = 0; it < 8; it++) {
            int job = bid * 32 + sg * 8 + it;
            int m0 = (job >> 3) * 64, n0 = (job & 7) * 64;
            mma_tile64(g_keys16, g_Wk16, bk, g_kproj16, A_, A_, m0, n0, stid, sA, sB);
        }
    }
    gridsync(sc);
    // load this block's kproj cache (rows 0..NC-1 of batch bid)
    {
        const uint4* src = (const uint4*)(g_kproj16 + (size_t)bid * S_ * A_);
        uint4* dst = (uint4*)(dyn + SM_KC_OFF);
        #pragma unroll 1
        for (int i = tid; i < NC * 64; i += 1024) dst[i] = src[i];
    }
    // load this block's Wcat slice (16 rows x 1024) into resident smem, per-kc tiles
    {
        int n0 = bid * 16;
        #pragma unroll
        for (int r = 0; r < 2; r++) {
            int idx = tid + r * 1024;               // 0..2047
            int kc = idx >> 8, rem = idx & 255;
            int row = rem >> 4, ch = rem & 15;
            int chs = ch ^ (row & 7);
            *(uint4*)(dyn + SM_WCAT_OFF + kc * 4096 + row * 256 + chs * 16) =
                *(const uint4*)(g_Wcat16 + (size_t)(n0 + row) * KX + kc * 128 + ch * 8);
        }
    }
    __syncthreads();

    for (int t = 0; t < T_; t++) {
        // ==== PA: qw (blocks 0-63, n-tile 8), out[t-1] (blocks 64-95, n-tile 8)
        // idle blocks (96-127, and 64-95 at t=0) prefetch their PB keys early
        bool did_early_prefetch = false;
        if (bid < 64) {
            int n0 = bid * 8;
            mma_gemm_n8(g_h16, H_, g_Wcomb16, H_, n0, H_, dyn, sb);
            int b = tid >> 3, nl = tid & 7;
            float s = g_bqc[n0 + nl];
            #pragma unroll
            for (int kg = 0; kg < 8; kg++) s += sRbuf[kg * 1024 + b * 8 + nl];
            g_qw[b * A_ + n0 + nl] = s;
        } else if (bid < 96 && t > 0) {
            int n0 = (bid - 64) * 8;
            mma_gemm_n8(g_h16, H_, g_Wout16, H_, n0, H_, dyn, sb);
            int b = tid >> 3, nl = tid & 7;
            float s = bout[n0 + nl];
            #pragma unroll
            for (int kg = 0; kg < 8; kg++) s += sRbuf[kg * 1024 + b * 8 + nl];
            out[((size_t)b * T_ + (t - 1)) * V_ + n0 + nl] = s;
        } else {
            // idle in PA: staging smem unused — start PB keys prefetch now
            const __half* kbase = g_keys16 + (size_t)bid * S_ * A_;
            #pragma unroll
            for (int r = 0; r < 5; r++) {
                int idx = tid + r * 1024;
                if (idx < KP * 64) {
                    int row = idx >> 6, cg = idx & 63;
                    cpasync16(sb + row * 1024 + cg * 16,
                              kbase + (size_t)row * A_ + cg * 8);
                }
            }
            CP_COMMIT();
            did_early_prefetch = true;
        }
        gridsync(sc);

        // ==== PB: attention for batch b = bid ====
        {
            const int b = bid;
            // prefetch first KP keys rows (skip if already issued during PA)
            if (!did_early_prefetch) {
                const __half* kbase = g_keys16 + (size_t)b * S_ * A_;
                #pragma unroll
                for (int r = 0; r < 5; r++) {
                    int idx = tid + r * 1024;       // KP*64 = 4608 chunks
                    if (idx < KP * 64) {
                        int row = idx >> 6, cg = idx & 63;
                        cpasync16(sb + row * 1024 + cg * 16,
                                  kbase + (size_t)row * A_ + cg * 8);
                    }
                }
                CP_COMMIT();
            }
            if (tid < A_) { sQ[tid] = g_qw[b * A_ + tid]; sVa[tid] = va[tid]; }
            __syncthreads();

            __half2 q2[8], v2[8];
            {
                const float4* q4 = (const float4*)(sQ + lane * 16);
                const float4* v4 = (const float4*)(sVa + lane * 16);
                #pragma unroll
                for (int i = 0; i < 4; i++) {
                    float4 qv = q4[i], vv = v4[i];
                    q2[2*i]   = __floats2half2_rn(qv.x, qv.y);
                    q2[2*i+1] = __floats2half2_rn(qv.z, qv.w);
                    v2[2*i]   = __floats2half2_rn(vv.x, vv.y);
                    v2[2*i+1] = __floats2half2_rn(vv.z, vv.w);
                }
            }
            #pragma unroll 2
            for (int r = 0; r < 8; r++) {
                int j = wp * 8 + r;
                const uint4* rowp = (j < NC)
                    ? (const uint4*)(dyn + SM_KC_OFF + j * 1024)
                    : (const uint4*)(g_kproj16 + ((size_t)b * S_ + j) * A_);
                uint4 d0 = rowp[lane * 2];
                uint4 d1 = rowp[lane * 2 + 1];
                const __half2* h0 = (const __half2*)&d0;
                const __half2* h1 = (const __half2*)&d1;
                float acc = 0.f;
                #pragma unroll
                for (int i = 0; i < 4; i++) {
                    __half2 p0 = __hmul2(v2[i],     ath_tanh_h2(__hadd2(h0[i], q2[i])));
                    __half2 p1 = __hmul2(v2[4 + i], ath_tanh_h2(__hadd2(h1[i], q2[4 + i])));
                    float2 f0 = __half22float2(p0);
                    float2 f1 = __half22float2(p1);
                    acc += (f0.x + f0.y) + (f1.x + f1.y);
                }
                acc = wsum(acc);
                if (lane == 0) sS[j] = acc;
            }
            __syncthreads();

            float v = 0.f, e = 0.f;
            if (tid < 256) {
                v = sS[tid];
                float m = wmax(v);
                if (lane == 0) sRed[wp] = m;
            }
            __syncthreads();
            if (tid < 256) {
                float m = sRed[0];
                #pragma unroll
                for (int i = 1; i < 8; i++) m = fmaxf(m, sRed[i]);
                e = expf(v - m);
                float s = wsum(e);
                if (lane == 0) sRedB[wp] = s;
            }
            __syncthreads();
            if (tid < 256) {
                float s = sRedB[0];
                #pragma unroll
                for (int i = 1; i < 8; i++) s += sRedB[i];
                sS[tid] = e / s;
            }
            CP_WAIT(0);
            __syncthreads();

            // context: wide uint4 loads; rows < KP come from smem prefetch
            {
                int cg = tid & 63, rg = tid >> 6;
                const uint4* kb4 = (const uint4*)(g_keys16 + (size_t)b * S_ * A_) + cg;
                float facc[8];
                #pragma unroll
                for (int i = 0; i < 8; i++) facc[i] = 0.f;
                #pragma unroll
                for (int r = 0; r < 16; r++) {
                    int j = rg * 16 + r;
                    uint4 kv = (j < KP)
                        ? *(const uint4*)(dyn + j * 1024 + cg * 16)
                        : kb4[(size_t)j * 64];
                    float w = sS[j];
                    const __half2* hh = (const __half2*)&kv;
                    #pragma unroll
                    for (int i = 0; i < 4; i++) {
                        float2 f = __half22float2(hh[i]);
                        facc[2*i]   = fmaf(w, f.x, facc[2*i]);
                        facc[2*i+1] = fmaf(w, f.y, facc[2*i+1]);
                    }
                }
                float* dst = sRbuf + rg * 512 + cg * 8;
                *(float4*)(dst)     = make_float4(facc[0], facc[1], facc[2], facc[3]);
                *(float4*)(dst + 4) = make_float4(facc[4], facc[5], facc[6], facc[7]);
            }
            __syncthreads();
            if (tid < 256) {
                int a0 = tid * 2;
                float sx = 0.f, sy = 0.f;
                #pragma unroll
                for (int rg2 = 0; rg2 < 16; rg2++) {
                    float2 p = *(const float2*)(sRbuf + rg2 * 512 + a0);
                    sx += p.x; sy += p.y;
                }
                ((__half2*)(g_Xh + (size_t)b * KX))[tid] =
                    __floats2half2_rn(sx, sy);
            }
        }
        gridsync(sc);

        // ==== PC: gates slice n0 = bid*16, K=1024; A pipelined, B resident ====
        {
            const int n0 = bid * 16;
            const int mg = wp >> 3, kg = wp & 7;
            float cfr[2][2][4];
            #pragma unroll
            for (int i = 0; i < 2; i++)
                #pragma unroll
                for (int j = 0; j < 2; j++)
                    #pragma unroll
                    for (int q = 0; q < 4; q++) cfr[i][j][q] = 0.f;

            // prefetch A stage 0
            {
                #pragma unroll
                for (int r = 0; r < 2; r++) {
                    int idx = tid + r * 1024;
                    int row = idx >> 4, ch = idx & 15, chs = ch ^ (row & 7);
                    cpasync16(sb + SM_A0 + row * 256 + chs * 16,
                              g_Xh + (size_t)row * KX + ch * 8);
                }
                CP_COMMIT();
            }

            for (int kc = 0; kc < 8; kc++) {
                if (kc < 7) {
                    int buf = (kc + 1) & 1;
                    #pragma unroll
                    for (int r = 0; r < 2; r++) {
                        int idx = tid + r * 1024;
                        int row = idx >> 4, ch = idx & 15, chs = ch ^ (row & 7);
                        cpasync16(sb + (buf ? SM_A1 : SM_A0) + row * 256 + chs * 16,
                                  g_Xh + (size_t)row * KX + (kc + 1) * 128 + ch * 8);
                    }
                    CP_COMMIT();
                    CP_WAIT(1);
                } else {
                    CP_WAIT(0);
                }
                __syncthreads();
                uint32_t abase = sb + ((kc & 1) ? SM_A1 : SM_A0);
                uint32_t bbase = sb + SM_WCAT_OFF + kc * 4096;   // resident Wcat tile
                uint32_t a0[4], a1[4], bb[4];
                int s = kg;
                int row = mg * 32 + (lane & 15);
                int ch = (s * 2 + (lane >> 4)) ^ (row & 7);
                ldmx4(a0, abase + row * 256 + ch * 16);
                row += 16; ch = (s * 2 + (lane >> 4)) ^ (row & 7);
                ldmx4(a1, abase + row * 256 + ch * 16);
                int n = ((lane >> 4) << 3) + (lane & 7);
                ch = (s * 2 + ((lane >> 3) & 1)) ^ (n & 7);
                ldmx4(bb, bbase + n * 256 + ch * 16);
                mma16816(cfr[0][0], a0, bb[0], bb[1]);
                mma16816(cfr[0][1], a0, bb[2], bb[3]);
                mma16816(cfr[1][0], a1, bb[0], bb[1]);
                mma16816(cfr[1][1], a1, bb[2], bb[3]);
                __syncthreads();
            }
            float* buf = sRbuf + kg * (128 * 16);
            int g = lane >> 2, tt = lane & 3;
            #pragma unroll
            for (int mf = 0; mf < 2; mf++)
                #pragma unroll
                for (int nf = 0; nf < 2; nf++) {
                    int r0 = mg * 32 + mf * 16 + g;
                    int cc = nf * 8 + 2 * tt;
                    float* c = cfr[mf][nf];
                    *(float2*)(buf + r0 * 16 + cc) = make_float2(c[0], c[1]);
                    *(float2*)(buf + (r0 + 8) * 16 + cc) = make_float2(c[2], c[3]);
                }
            __syncthreads();
            if (tid < 512) {
                int b = tid >> 2, jl = tid & 3;
                float4 s0 = make_float4(0.f, 0.f, 0.f, 0.f);
                #pragma unroll
                for (int kg2 = 0; kg2 < 8; kg2++) {
                    float4 v4 = *(const float4*)(sRbuf + kg2 * 2048 + b * 16 + jl * 4);
                    s0.x += v4.x; s0.y += v4.y; s0.z += v4.z; s0.w += v4.w;
                }
                int n = n0 + jl * 4;
                int lbl = labels[b * T_ + (t > 0 ? t - 1 : 0)];
                float4 bc = *(const float4*)(g_bcombIl + n);
                float4 wv = *(const float4*)(g_WihVTil + (size_t)lbl * NG + n);
                s0.x += bc.x + wv.x; s0.y += bc.y + wv.y;
                s0.z += bc.z + wv.z; s0.w += bc.w + wv.w;
                int j = bid * 4 + jl;
                float c = g_c[b * H_ + j];
                float cn = sigm(s0.y) * c + sigm(s0.x) * tanhf(s0.z);
                float hn = sigm(s0.w) * tanhf(cn);
                g_c[b * H_ + j] = cn;
                __half hh = __float2half(hn);
                g_h16[b * H_ + j] = hh;
                g_Xh[(size_t)b * KX + A_ + j] = hh;
            }
        }
        gridsync(sc);
    }

    // final out row t = T-1
    if (bid >= 64 && bid < 96) {
        int n0 = (bid - 64) * 8;
        mma_gemm_n8(g_h16, H_, g_Wout16, H_, n0, H_, dyn, sb);
        int b = tid >> 3, nl = tid & 7;
        float s = bout[n0 + nl];
        #pragma unroll
        for (int kg = 0; kg < 8; kg++) s += sRbuf[kg * 1024 + b * 8 + nl];
        out[((size_t)b * T_ + (T_ - 1)) * V_ + n0 + nl] = s;
    }
}

// ---------------- host driver ----------------
extern "C" void kernel_launch(void* const* d_in, const int* in_sizes, int n_in,
                              void* d_out, int out_size) {
    (void)in_sizes; (void)n_in; (void)out_size;
    const float* feats = (const float*)d_in[0];
    const int*   labels= (const int*)  d_in[1];
    const float* Ic_w  = (const float*)d_in[2];
    const float* Ic_b  = (const float*)d_in[3];
    const float* Hc_w  = (const float*)d_in[4];
    const float* Hc_b  = (const float*)d_in[5];
    const float* Wq    = (const float*)d_in[6];
    const float* bq    = (const float*)d_in[7];
    const float* Wk    = (const float*)d_in[8];
    const float* bk    = (const float*)d_in[9];
    const float* va    = (const float*)d_in[10];
    const float* W_ih  = (const float*)d_in[11];
    const float* b_ih  = (const float*)d_in[12];
    const float* W_hh  = (const float*)d_in[13];
    const float* b_hh  = (const float*)d_in[14];
    const float* Wout  = (const float*)d_in[15];
    const float* bout  = (const float*)d_in[16];
    float* out = (float*)d_out;

    __half *p_feats16, *p_keys16, *p_Icw16, *p_Wcomb16;
    cudaGetSymbolAddress((void**)&p_feats16, g_feats16);
    cudaGetSymbolAddress((void**)&p_keys16,  g_keys16);
    cudaGetSymbolAddress((void**)&p_Icw16,   g_Icw16);
    cudaGetSymbolAddress((void**)&p_Wcomb16, g_Wcomb16);

    cudaFuncSetAttribute(persist, cudaFuncAttributeMaxDynamicSharedMemorySize, SMEM_DYN);

    // launch 1: all elementwise prep fused
    k_prep_all<<<(B_*S_*C_)/256, 256>>>(feats, Ic_w, Wk, Wout, W_ih, W_hh,
                                        b_ih, b_hh, Wq, bq, Hc_b);
    // launch 2: Wcomb = Wq @ Hc_w  (NN, fp32 in, fp16 out)
    gemm_wcomb_nn<<<dim3(H_/64, A_/64), 256>>>(Wq, Hc_w, p_Wcomb16);
    // launch 3: keys16 = feats @ Ic_w^T + Ic_b
    mma_pre<<<dim3(A_/64, (B_*S_)/64), 256>>>(p_feats16, p_Icw16, Ic_b, p_keys16, C_, A_);
    // launch 4: persistent decode (prologue computes kproj, then 128 steps)
    persist<<<NBLK, 1024, SMEM_DYN>>>(labels, va, bk, bout, out);
}

// round 15
// speedup vs baseline: 1.1375x; 1.0396x over previous
#include <cuda_runtime.h>
#include <cuda_fp16.h>
#include <cstdint>

#define B_ 128
#define S_ 256
#define C_ 512
#define T_ 128
#define V_ 256
#define H_ 512
#define A_ 512
#define NG 2048   /* 4*H */
#define KX 1024   /* A + H */
#define NBLK 128

// smem layout
#define SM_A0 0
#define SM_A1 32768
#define SM_B0 65536
#define SM_B1 69632
#define SM_R_OFF 73728          /* 64KB partials */
#define SM_Q_OFF 139264
#define SM_S_OFF 143360
#define SM_RED_OFF 144384
#define SM_REDB_OFF 144512
#define SM_WCAT_OFF 144640      /* 32KB resident Wcat slice (8 tiles of 4KB) */
#define SM_KC_OFF 177408
#define NC 52                   /* cached kproj rows per block */
#define KP 72                   /* keys rows prefetched into A0.. during PB */
#define SMEM_DYN (SM_KC_OFF + NC*1024)   /* 230656 */

// ---------------- device scratch ----------------
__device__ __half g_feats16[B_*S_*C_];
__device__ __half g_keys16 [B_*S_*A_];
__device__ __half g_kproj16[B_*S_*A_];
__device__ __half g_Icw16  [A_*C_];
__device__ __half g_Wk16   [A_*A_];
__device__ __half g_Wcomb16[A_*H_];   // (Wq @ Hc_w) fp16
__device__ float  g_bqc    [A_];      // bq + Wq @ Hc_b
__device__ __half g_Wcat16 [NG*KX];   // interleaved-gate [W_ih[:,V:] | W_hh] fp16
__device__ float  g_bcombIl[NG];
__device__ float  g_WihVTil[V_*NG];
__device__ __half g_Wout16 [V_*H_];
__device__ __half g_h16    [B_*H_];
__device__ float  g_c      [B_*H_];
__device__ __half g_Xh     [B_*KX];   // [ctx | h] fp16
__device__ float  g_qw     [B_*A_];
__device__ unsigned g_sync;

// ---------------- helpers ----------------
__device__ __forceinline__ float wsum(float v) {
    #pragma unroll
    for (int o = 16; o > 0; o >>= 1) v += __shfl_down_sync(0xffffffffu, v, o);
    return v;
}
__device__ __forceinline__ float wmax(float v) {
    #pragma unroll
    for (int o = 16; o > 0; o >>= 1) v = fmaxf(v, __shfl_down_sync(0xffffffffu, v, o));
    return v;
}
__device__ __forceinline__ float sigm(float x) { return 1.f / (1.f + expf(-x)); }
__device__ __forceinline__ __half2 ath_tanh_h2(__half2 x) {
    __half2 y;
    asm("tanh.approx.f16x2 %0, %1;"
        : "=r"(*(uint32_t*)&y) : "r"(*(uint32_t*)&x));
    return y;
}
__device__ __forceinline__ void ldmx4(uint32_t* r, uint32_t addr) {
    asm volatile("ldmatrix.sync.aligned.m8n8.x4.shared.b16 {%0,%1,%2,%3}, [%4];"
        : "=r"(r[0]), "=r"(r[1]), "=r"(r[2]), "=r"(r[3]) : "r"(addr));
}
__device__ __forceinline__ void ldmx2(uint32_t &r0, uint32_t &r1, uint32_t addr) {
    asm volatile("ldmatrix.sync.aligned.m8n8.x2.shared.b16 {%0,%1}, [%2];"
        : "=r"(r0), "=r"(r1) : "r"(addr));
}
__device__ __forceinline__ void mma16816(float* c, const uint32_t* a, uint32_t b0, uint32_t b1) {
    asm volatile("mma.sync.aligned.m16n8k16.row.col.f32.f16.f16.f32 "
        "{%0,%1,%2,%3}, {%4,%5,%6,%7}, {%8,%9}, {%0,%1,%2,%3};"
        : "+f"(c[0]), "+f"(c[1]), "+f"(c[2]), "+f"(c[3])
        : "r"(a[0]), "r"(a[1]), "r"(a[2]), "r"(a[3]), "r"(b0), "r"(b1));
}
__device__ __forceinline__ void cpasync16(uint32_t saddr, const void* gaddr) {
    asm volatile("cp.async.cg.shared.global [%0], [%1], 16;"
                 :: "r"(saddr), "l"(gaddr) : "memory");
}
#define CP_COMMIT() asm volatile("cp.async.commit_group;" ::: "memory")
#define CP_WAIT(n)  asm volatile("cp.async.wait_group %0;" :: "n"(n) : "memory")

// -------- 64x64 mma tile (8 warps / 256 threads), Ch = A@B^T + bias --------
__device__ void mma_tile64(const __half* __restrict__ Ag, const __half* __restrict__ Bg,
                           const float* __restrict__ bias, __half* __restrict__ Ch,
                           int K, int ldc, int m0, int n0, int stid,
                           char* sA, char* sB)
{
    const int lane = stid & 31, wid8 = stid >> 5;
    const int mg = wid8 >> 2, ng = wid8 & 3;
    uint32_t sa = (uint32_t)__cvta_generic_to_shared(sA);
    uint32_t sbp = (uint32_t)__cvta_generic_to_shared(sB);

    float cfr[2][2][4];
    #pragma unroll
    for (int i = 0; i < 2; i++)
        #pragma unroll
        for (int j = 0; j < 2; j++)
            #pragma unroll
            for (int q = 0; q < 4; q++) cfr[i][j][q] = 0.f;

    for (int kc = 0; kc < K / 64; kc++) {
        __syncthreads();
        #pragma unroll
        for (int r = 0; r < 2; r++) {
            int idx = stid + r * 256;
            int row = idx >> 3, ch = idx & 7;
            int chs = ch ^ (row & 7);
            *(uint4*)(sA + row * 128 + chs * 16) =
                *(const uint4*)(Ag + (size_t)(m0 + row) * K + kc * 64 + ch * 8);
            *(uint4*)(sB + row * 128 + chs * 16) =
                *(const uint4*)(Bg + (size_t)(n0 + row) * K + kc * 64 + ch * 8);
        }
        __syncthreads();
        #pragma unroll
        for (int s = 0; s < 4; s++) {
            uint32_t a0[4], a1[4], bb[4];
            int row = mg * 32 + (lane & 15);
            int ch = (s * 2 + (lane >> 4)) ^ (row & 7);
            ldmx4(a0, sa + row * 128 + ch * 16);
            row += 16; ch = (s * 2 + (lane >> 4)) ^ (row & 7);
            ldmx4(a1, sa + row * 128 + ch * 16);
            int n = ng * 16 + ((lane >> 4) << 3) + (lane & 7);
            ch = (s * 2 + ((lane >> 3) & 1)) ^ (n & 7);
            ldmx4(bb, sbp + n * 128 + ch * 16);
            mma16816(cfr[0][0], a0, bb[0], bb[1]);
            mma16816(cfr[0][1], a0, bb[2], bb[3]);
            mma16816(cfr[1][0], a1, bb[0], bb[1]);
            mma16816(cfr[1][1], a1, bb[2], bb[3]);
        }
    }
    int g = lane >> 2, t = lane & 3;
    #pragma unroll
    for (int mf = 0; mf < 2; mf++)
        #pragma unroll
        for (int nf = 0; nf < 2; nf++) {
            int row = m0 + mg * 32 + mf * 16 + g;
            int col = n0 + ng * 16 + nf * 8 + 2 * t;
            float b0v = bias ? bias[col] : 0.f, b1v = bias ? bias[col + 1] : 0.f;
            float* c = cfr[mf][nf];
            *(__half2*)(Ch + (size_t)row * ldc + col) =
                __floats2half2_rn(c[0] + b0v, c[1] + b1v);
            *(__half2*)(Ch + (size_t)(row + 8) * ldc + col) =
                __floats2half2_rn(c[2] + b0v, c[3] + b1v);
        }
}

__global__ void mma_pre(const __half* __restrict__ Ag, const __half* __restrict__ Bg,
                        const float* __restrict__ bias, __half* __restrict__ Ch,
                        int K, int ldc)
{
    __shared__ __align__(16) char sA[8192];
    __shared__ __align__(16) char sB[8192];
    mma_tile64(Ag, Bg, bias, Ch, K, ldc, blockIdx.y * 64, blockIdx.x * 64,
               threadIdx.x, sA, sB);
}

// -------- NN GEMM for Wcomb: C[a][k] = sum_m Wq[a][m] * Hc_w[m][k], fp16 out --
__global__ void gemm_wcomb_nn(const float* __restrict__ Wq, const float* __restrict__ Hcw,
                              __half* __restrict__ Ch)
{
    __shared__ __align__(16) float As[16][68];
    __shared__ __align__(16) float Bs[16][68];
    const int tid = threadIdx.x;
    const int tx = tid & 15, ty = tid >> 4;
    const int n0 = blockIdx.x * 64, m0 = blockIdx.y * 64;
    float acc[4][4];
    #pragma unroll
    for (int i = 0; i < 4; i++)
        #pragma unroll
        for (int j = 0; j < 4; j++) acc[i][j] = 0.f;
    const int lr = tid >> 2, lc = (tid & 3) * 4;
    const int br = tid >> 4, bc = (tid & 15) * 4;
    for (int kb = 0; kb < A_; kb += 16) {
        float4 av = *(const float4*)(Wq + (size_t)(m0 + lr) * A_ + kb + lc);
        As[lc+0][lr] = av.x; As[lc+1][lr] = av.y; As[lc+2][lr] = av.z; As[lc+3][lr] = av.w;
        float4 bv = *(const float4*)(Hcw + (size_t)(kb + br) * H_ + n0 + bc);
        Bs[br][bc+0] = bv.x; Bs[br][bc+1] = bv.y; Bs[br][bc+2] = bv.z; Bs[br][bc+3] = bv.w;
        __syncthreads();
        #pragma unroll
        for (int kk = 0; kk < 16; kk++) {
            float4 a4 = *(const float4*)&As[kk][ty * 4];
            float4 b4 = *(const float4*)&Bs[kk][tx * 4];
            float a_[4] = {a4.x, a4.y, a4.z, a4.w};
            float b_[4] = {b4.x, b4.y, b4.z, b4.w};
            #pragma unroll
            for (int i = 0; i < 4; i++)
                #pragma unroll
                for (int j = 0; j < 4; j++) acc[i][j] = fmaf(a_[i], b_[j], acc[i][j]);
        }
        __syncthreads();
    }
    #pragma unroll
    for (int i = 0; i < 4; i++)
        #pragma unroll
        for (int j = 0; j < 4; j++)
            Ch[(size_t)(m0 + ty * 4 + i) * H_ + n0 + tx * 4 + j] = __float2half(acc[i][j]);
}

// ---------------- fused one-time prep (single launch) ----------------
__global__ void k_prep_all(const float* __restrict__ feats, const float* __restrict__ Ic_w,
                           const float* __restrict__ Wk, const float* __restrict__ Wout,
                           const float* __restrict__ W_ih, const float* __restrict__ W_hh,
                           const float* __restrict__ b_ih, const float* __restrict__ b_hh,
                           const float* __restrict__ Wq, const float* __restrict__ bq,
                           const float* __restrict__ Hcb)
{
    long idx = (long)blockIdx.x * 256 + threadIdx.x;
    if (idx < (long)B_*S_*C_) g_feats16[idx] = __float2half(feats[idx]);
    if (idx < A_*C_)  g_Icw16[idx]  = __float2half(Ic_w[idx]);
    if (idx < A_*A_)  g_Wk16[idx]   = __float2half(Wk[idx]);
    if (idx < V_*H_)  g_Wout16[idx] = __float2half(Wout[idx]);
    if (idx < (long)NG*KX) {
        int nil = (int)(idx >> 10), k = (int)(idx & 1023);
        int n = (nil & 3) * H_ + (nil >> 2);
        float v = (k < A_) ? W_ih[(size_t)n * (V_ + A_) + V_ + k]
                           : W_hh[(size_t)n * H_ + (k - A_)];
        g_Wcat16[idx] = __float2half(v);
    }
    if (idx < (long)V_*NG) {
        int v = (int)(idx >> 11), nil = (int)(idx & 2047);
        int n = (nil & 3) * H_ + (nil >> 2);
        g_WihVTil[idx] = W_ih[(size_t)n * (V_ + A_) + v];
    }
    if (idx < B_*H_) {
        g_h16[idx] = __float2half(0.f);
        g_c[idx] = 0.f;
        int b = (int)(idx >> 9), j = (int)(idx & 511);
        g_Xh[b * KX + A_ + j] = __float2half(0.f);
    }
    if (idx < NG) {
        int nn = ((int)idx & 3) * H_ + ((int)idx >> 2);
        g_bcombIl[idx] = b_ih[nn] + b_hh[nn];
    }
    if (idx < A_) {
        float s = bq[idx];
        for (int m = 0; m < A_; m++) s += Wq[idx * A_ + m] * Hcb[m];
        g_bqc[idx] = s;
    }
    if (idx == 0) g_sync = 0u;
}

// ---------------- single-counter grid sync ----------------
__device__ __forceinline__ void gridsync(unsigned &sc) {
    __syncthreads();
    sc += NBLK;
    if (threadIdx.x == 0) {
        asm volatile("red.release.gpu.global.add.u32 [%0], 1;" :: "l"(&g_sync) : "memory");
        unsigned v;
        do {
            asm volatile("ld.acquire.gpu.global.u32 %0, [%1];" : "=r"(v) : "l"(&g_sync) : "memory");
        } while (v < sc);
    }
    __syncthreads();
}

// mma GEMM (double-buffered cp.async): partials for C[128, n0..n0+8) into smem
__device__ __forceinline__ void mma_gemm_n8(const __half* __restrict__ Ag, int lda,
        const __half* __restrict__ Bg, int ldb, int n0, int K,
        char* dyn, uint32_t sb)
{
    const int tid = threadIdx.x, lane = tid & 31, wid = tid >> 5;
    const int mg = wid >> 3, kg = wid & 7;
    float cfr[2][4];
    #pragma unroll
    for (int i = 0; i < 2; i++)
        #pragma unroll
        for (int q = 0; q < 4; q++) cfr[i][q] = 0.f;

    const int nkc = K / 128;

    // prefetch stage 0
    {
        #pragma unroll
        for (int r = 0; r < 2; r++) {
            int idx = tid + r * 1024;
            int row = idx >> 4, ch = idx & 15, chs = ch ^ (row & 7);
            cpasync16(sb + SM_A0 + row * 256 + chs * 16,
                      Ag + (size_t)row * lda + ch * 8);
        }
        if (tid < 128) {
            int row = tid >> 4, ch = tid & 15, chs = ch ^ (row & 7);
            cpasync16(sb + SM_B0 + row * 256 + chs * 16,
                      Bg + (size_t)(n0 + row) * ldb + ch * 8);
        }
        CP_COMMIT();
    }

    for (int kc = 0; kc < nkc; kc++) {
        if (kc + 1 < nkc) {
            int buf = (kc + 1) & 1;
            #pragma unroll
            for (int r = 0; r < 2; r++) {
                int idx = tid + r * 1024;
                int row = idx >> 4, ch = idx & 15, chs = ch ^ (row & 7);
                cpasync16(sb + (buf ? SM_A1 : SM_A0) + row * 256 + chs * 16,
                          Ag + (size_t)row * lda + (kc + 1) * 128 + ch * 8);
            }
            if (tid < 128) {
                int row = tid >> 4, ch = tid & 15, chs = ch ^ (row & 7);
                cpasync16(sb + (buf ? SM_B1 : SM_B0) + row * 256 + chs * 16,
                          Bg + (size_t)(n0 + row) * ldb + (kc + 1) * 128 + ch * 8);
            }
            CP_COMMIT();
            CP_WAIT(1);
        } else {
            CP_WAIT(0);
        }
        __syncthreads();
        uint32_t abase = sb + ((kc & 1) ? SM_A1 : SM_A0);
        uint32_t bbase = sb + ((kc & 1) ? SM_B1 : SM_B0);
        uint32_t a0[4], a1[4], b0, b1;
        int s = kg;
        int row = mg * 32 + (lane & 15);
        int ch = (s * 2 + (lane >> 4)) ^ (row & 7);
        ldmx4(a0, abase + row * 256 + ch * 16);
        row += 16; ch = (s * 2 + (lane >> 4)) ^ (row & 7);
        ldmx4(a1, abase + row * 256 + ch * 16);
        int n = lane & 7;
        ch = (s * 2 + ((lane >> 3) & 1)) ^ (n & 7);
        ldmx2(b0, b1, bbase + n * 256 + ch * 16);
        mma16816(cfr[0], a0, b0, b1);
        mma16816(cfr[1], a1, b0, b1);
        __syncthreads();
    }
    float* buf = (float*)(dyn + SM_R_OFF) + kg * (128 * 8);
    int g = lane >> 2, t = lane & 3;
    #pragma unroll
    for (int mf = 0; mf < 2; mf++) {
        int r0 = mg * 32 + mf * 16 + g;
        *(float2*)(buf + r0 * 8 + 2 * t) = make_float2(cfr[mf][0], cfr[mf][1]);
        *(float2*)(buf + (r0 + 8) * 8 + 2 * t) = make_float2(cfr[mf][2], cfr[mf][3]);
    }
    __syncthreads();
}

__global__ void __launch_bounds__(1024, 1) persist(
        const int* __restrict__ labels, const float* __restrict__ va,
        const float* __restrict__ bk, const float* __restrict__ bout,
        float* __restrict__ out)
{
    extern __shared__ __align__(16) char dyn[];
    const uint32_t sb = (uint32_t)__cvta_generic_to_shared(dyn);
    float* sRbuf = (float*)(dyn + SM_R_OFF);
    float* sQ    = (float*)(dyn + SM_Q_OFF);
    float* sS    = (float*)(dyn + SM_S_OFF);
    float* sRed  = (float*)(dyn + SM_RED_OFF);
    float* sRedB = (float*)(dyn + SM_REDB_OFF);

    const int bid = blockIdx.x, tid = threadIdx.x;
    const int lane = tid & 31, wp = tid >> 5;
    unsigned sc = 0;

    // va as half2 registers, loaded ONCE (step-invariant)
    __half2 v2[8];
    {
        const float4* v4 = (const float4*)(va + lane * 16);
        #pragma unroll
        for (int i = 0; i < 4; i++) {
            float4 vv = v4[i];
            v2[2*i]   = __floats2half2_rn(vv.x, vv.y);
            v2[2*i+1] = __floats2half2_rn(vv.z, vv.w);
        }
    }
    // persistent LSTM cell state in registers (thread tid<512 owns (b=tid>>2, j=bid*4+(tid&3)))
    float c_reg = 0.f;
    float4 bc_reg = make_float4(0.f, 0.f, 0.f, 0.f);
    if (tid < 512) {
        int jl = tid & 3;
        bc_reg = *(const float4*)(g_bcombIl + bid * 16 + jl * 4);
    }

    // ==== prologue: kproj = keys @ Wk^T + bk (4096 tiles, 4 sub-jobs/block) ====
    {
        int sg = tid >> 8, stid = tid & 255;
        char* sA = dyn + sg * 16384;
        char* sB = sA + 8192;
        #pragma unroll 1
        for (int it = 0; it < 8; it++) {
            int job = bid * 32 + sg * 8 + it;
            int m0 = (job >> 3) * 64, n0 = (job & 7) * 64;
            mma_tile64(g_keys16, g_Wk16, bk, g_kproj16, A_, A_, m0, n0, stid, sA, sB);
        }
    }
    gridsync(sc);
    // load this block's kproj cache (rows 0..NC-1 of batch bid)
    {
        const uint4* src = (const uint4*)(g_kproj16 + (size_t)bid * S_ * A_);
        uint4* dst = (uint4*)(dyn + SM_KC_OFF);
        #pragma unroll 1
        for (int i = tid; i < NC * 64; i += 1024) dst[i] = src[i];
    }
    // load this block's Wcat slice (16 rows x 1024) into resident smem, per-kc tiles
    {
        int n0 = bid * 16;
        #pragma unroll
        for (int r = 0; r < 2; r++) {
            int idx = tid + r * 1024;               // 0..2047
            int kc = idx >> 8, rem = idx & 255;
            int row = rem >> 4, ch = rem & 15;
            int chs = ch ^ (row & 7);
            *(uint4*)(dyn + SM_WCAT_OFF + kc * 4096 + row * 256 + chs * 16) =
                *(const uint4*)(g_Wcat16 + (size_t)(n0 + row) * KX + kc * 128 + ch * 8);
        }
    }
    __syncthreads();

    for (int t = 0; t < T_; t++) {
        // ==== PA: qw (blocks 0-63, n-tile 8), out[t-1] (blocks 64-95, n-tile 8)
        bool did_early_prefetch = false;
        if (bid < 64) {
            int n0 = bid * 8;
            mma_gemm_n8(g_h16, H_, g_Wcomb16, H_, n0, H_, dyn, sb);
            int b = tid >> 3, nl = tid & 7;
            float s = g_bqc[n0 + nl];
            #pragma unroll
            for (int kg = 0; kg < 8; kg++) s += sRbuf[kg * 1024 + b * 8 + nl];
            g_qw[b * A_ + n0 + nl] = s;
        } else if (bid < 96 && t > 0) {
            int n0 = (bid - 64) * 8;
            mma_gemm_n8(g_h16, H_, g_Wout16, H_, n0, H_, dyn, sb);
            int b = tid >> 3, nl = tid & 7;
            float s = bout[n0 + nl];
            #pragma unroll
            for (int kg = 0; kg < 8; kg++) s += sRbuf[kg * 1024 + b * 8 + nl];
            out[((size_t)b * T_ + (t - 1)) * V_ + n0 + nl] = s;
        } else {
            // idle in PA: staging smem unused — start PB keys prefetch now
            const __half* kbase = g_keys16 + (size_t)bid * S_ * A_;
            #pragma unroll
            for (int r = 0; r < 5; r++) {
                int idx = tid + r * 1024;
                if (idx < KP * 64) {
                    int row = idx >> 6, cg = idx & 63;
                    cpasync16(sb + row * 1024 + cg * 16,
                              kbase + (size_t)row * A_ + cg * 8);
                }
            }
            CP_COMMIT();
            did_early_prefetch = true;
        }
        gridsync(sc);

        // ==== PB: attention for batch b = bid ====
        {
            const int b = bid;
            if (!did_early_prefetch) {
                const __half* kbase = g_keys16 + (size_t)b * S_ * A_;
                #pragma unroll
                for (int r = 0; r < 5; r++) {
                    int idx = tid + r * 1024;       // KP*64 = 4608 chunks
                    if (idx < KP * 64) {
                        int row = idx >> 6, cg = idx & 63;
                        cpasync16(sb + row * 1024 + cg * 16,
                                  kbase + (size_t)row * A_ + cg * 8);
                    }
                }
                CP_COMMIT();
            }
            if (tid < A_) sQ[tid] = g_qw[b * A_ + tid];
            __syncthreads();

            __half2 q2[8];
            {
                const float4* q4 = (const float4*)(sQ + lane * 16);
                #pragma unroll
                for (int i = 0; i < 4; i++) {
                    float4 qv = q4[i];
                    q2[2*i]   = __floats2half2_rn(qv.x, qv.y);
                    q2[2*i+1] = __floats2half2_rn(qv.z, qv.w);
                }
            }
            #pragma unroll 2
            for (int r = 0; r < 8; r++) {
                int j = wp * 8 + r;
                const uint4* rowp = (j < NC)
                    ? (const uint4*)(dyn + SM_KC_OFF + j * 1024)
                    : (const uint4*)(g_kproj16 + ((size_t)b * S_ + j) * A_);
                uint4 d0 = rowp[lane * 2];
                uint4 d1 = rowp[lane * 2 + 1];
                const __half2* h0 = (const __half2*)&d0;
                const __half2* h1 = (const __half2*)&d1;
                float acc = 0.f;
                #pragma unroll
                for (int i = 0; i < 4; i++) {
                    __half2 p0 = __hmul2(v2[i],     ath_tanh_h2(__hadd2(h0[i], q2[i])));
                    __half2 p1 = __hmul2(v2[4 + i], ath_tanh_h2(__hadd2(h1[i], q2[4 + i])));
                    float2 f0 = __half22float2(p0);
                    float2 f1 = __half22float2(p1);
                    acc += (f0.x + f0.y) + (f1.x + f1.y);
                }
                acc = wsum(acc);
                if (lane == 0) sS[j] = acc;
            }
            __syncthreads();

            float v = 0.f, e = 0.f;
            if (tid < 256) {
                v = sS[tid];
                float m = wmax(v);
                if (lane == 0) sRed[wp] = m;
            }
            __syncthreads();
            if (tid < 256) {
                float m = sRed[0];
                #pragma unroll
                for (int i = 1; i < 8; i++) m = fmaxf(m, sRed[i]);
                e = expf(v - m);
                float s = wsum(e);
                if (lane == 0) sRedB[wp] = s;
            }
            __syncthreads();
            if (tid < 256) {
                float s = sRedB[0];
                #pragma unroll
                for (int i = 1; i < 8; i++) s += sRedB[i];
                sS[tid] = e / s;
            }
            CP_WAIT(0);
            __syncthreads();

            // context: wide uint4 loads; rows < KP come from smem prefetch
            {
                int cg = tid & 63, rg = tid >> 6;
                const uint4* kb4 = (const uint4*)(g_keys16 + (size_t)b * S_ * A_) + cg;
                float facc[8];
                #pragma unroll
                for (int i = 0; i < 8; i++) facc[i] = 0.f;
                #pragma unroll
                for (int r = 0; r < 16; r++) {
                    int j = rg * 16 + r;
                    uint4 kv = (j < KP)
                        ? *(const uint4*)(dyn + j * 1024 + cg * 16)
                        : kb4[(size_t)j * 64];
                    float w = sS[j];
                    const __half2* hh = (const __half2*)&kv;
                    #pragma unroll
                    for (int i = 0; i < 4; i++) {
                        float2 f = __half22float2(hh[i]);
                        facc[2*i]   = fmaf(w, f.x, facc[2*i]);
                        facc[2*i+1] = fmaf(w, f.y, facc[2*i+1]);
                    }
                }
                float* dst = sRbuf + rg * 512 + cg * 8;
                *(float4*)(dst)     = make_float4(facc[0], facc[1], facc[2], facc[3]);
                *(float4*)(dst + 4) = make_float4(facc[4], facc[5], facc[6], facc[7]);
            }
            __syncthreads();
            if (tid < 256) {
                int a0 = tid * 2;
                float sx = 0.f, sy = 0.f;
                #pragma unroll
                for (int rg2 = 0; rg2 < 16; rg2++) {
                    float2 p = *(const float2*)(sRbuf + rg2 * 512 + a0);
                    sx += p.x; sy += p.y;
                }
                ((__half2*)(g_Xh + (size_t)b * KX))[tid] =
                    __floats2half2_rn(sx, sy);
            }
        }
        gridsync(sc);

        // ==== PC: gates slice n0 = bid*16, K=1024; A pipelined, B resident ====
        {
            const int n0 = bid * 16;
            const int mg = wp >> 3, kg = wp & 7;

            // early-issue the label -> one-hot W_ih column chain (hidden by GEMM)
            float4 wv_reg = make_float4(0.f, 0.f, 0.f, 0.f);
            if (tid < 512) {
                int b = tid >> 2, jl = tid & 3;
                int lbl = labels[b * T_ + (t > 0 ? t - 1 : 0)];
                wv_reg = *(const float4*)(g_WihVTil + (size_t)lbl * NG + n0 + jl * 4);
            }

            float cfr[2][2][4];
            #pragma unroll
            for (int i = 0; i < 2; i++)
                #pragma unroll
                for (int j = 0; j < 2; j++)
                    #pragma unroll
                    for (int q = 0; q < 4; q++) cfr[i][j][q] = 0.f;

            // prefetch A stage 0
            {
                #pragma unroll
                for (int r = 0; r < 2; r++) {
                    int idx = tid + r * 1024;
                    int row = idx >> 4, ch = idx & 15, chs = ch ^ (row & 7);
                    cpasync16(sb + SM_A0 + row * 256 + chs * 16,
                              g_Xh + (size_t)row * KX + ch * 8);
                }
                CP_COMMIT();
            }

            for (int kc = 0; kc < 8; kc++) {
                if (kc < 7) {
                    int buf = (kc + 1) & 1;
                    #pragma unroll
                    for (int r = 0; r < 2; r++) {
                        int idx = tid + r * 1024;
                        int row = idx >> 4, ch = idx & 15, chs = ch ^ (row & 7);
                        cpasync16(sb + (buf ? SM_A1 : SM_A0) + row * 256 + chs * 16,
                                  g_Xh + (size_t)row * KX + (kc + 1) * 128 + ch * 8);
                    }
                    CP_COMMIT();
                    CP_WAIT(1);
                } else {
                    CP_WAIT(0);
                }
                __syncthreads();
                uint32_t abase = sb + ((kc & 1) ? SM_A1 : SM_A0);
                uint32_t bbase = sb + SM_WCAT_OFF + kc * 4096;   // resident Wcat tile
                uint32_t a0[4], a1[4], bb[4];
                int s = kg;
                int row = mg * 32 + (lane & 15);
                int ch = (s * 2 + (lane >> 4)) ^ (row & 7);
                ldmx4(a0, abase + row * 256 + ch * 16);
                row += 16; ch = (s * 2 + (lane >> 4)) ^ (row & 7);
                ldmx4(a1, abase + row * 256 + ch * 16);
                int n = ((lane >> 4) << 3) + (lane & 7);
                ch = (s * 2 + ((lane >> 3) & 1)) ^ (n & 7);
                ldmx4(bb, bbase + n * 256 + ch * 16);
                mma16816(cfr[0][0], a0, bb[0], bb[1]);
                mma16816(cfr[0][1], a0, bb[2], bb[3]);
                mma16816(cfr[1][0], a1, bb[0], bb[1]);
                mma16816(cfr[1][1], a1, bb[2], bb[3]);
                __syncthreads();
            }
            float* buf = sRbuf + kg * (128 * 16);
            int g = lane >> 2, tt = lane & 3;
            #pragma unroll
            for (int mf = 0; mf < 2; mf++)
                #pragma unroll
                for (int nf = 0; nf < 2; nf++) {
                    int r0 = mg * 32 + mf * 16 + g;
                    int cc = nf * 8 + 2 * tt;
                    float* c = cfr[mf][nf];
                    *(float2*)(buf + r0 * 16 + cc) = make_float2(c[0], c[1]);
                    *(float2*)(buf + (r0 + 8) * 16 + cc) = make_float2(c[2], c[3]);
                }
            __syncthreads();
            if (tid < 512) {
                int b = tid >> 2, jl = tid & 3;
                float4 s0 = make_float4(0.f, 0.f, 0.f, 0.f);
                #pragma unroll
                for (int kg2 = 0; kg2 < 8; kg2++) {
                    float4 v4 = *(const float4*)(sRbuf + kg2 * 2048 + b * 16 + jl * 4);
                    s0.x += v4.x; s0.y += v4.y; s0.z += v4.z; s0.w += v4.w;
                }
                s0.x += bc_reg.x + wv_reg.x; s0.y += bc_reg.y + wv_reg.y;
                s0.z += bc_reg.z + wv_reg.z; s0.w += bc_reg.w + wv_reg.w;
                int j = bid * 4 + jl;
                float cn = sigm(s0.y) * c_reg + sigm(s0.x) * tanhf(s0.z);
                float hn = sigm(s0.w) * tanhf(cn);
                c_reg = cn;
                __half hh = __float2half(hn);
                g_h16[b * H_ + j] = hh;
                g_Xh[(size_t)b * KX + A_ + j] = hh;
            }
        }
        gridsync(sc);
    }

    // final out row t = T-1
    if (bid >= 64 && bid < 96) {
        int n0 = (bid - 64) * 8;
        mma_gemm_n8(g_h16, H_, g_Wout16, H_, n0, H_, dyn, sb);
        int b = tid >> 3, nl = tid & 7;
        float s = bout[n0 + nl];
        #pragma unroll
        for (int kg = 0; kg < 8; kg++) s += sRbuf[kg * 1024 + b * 8 + nl];
        out[((size_t)b * T_ + (T_ - 1)) * V_ + n0 + nl] = s;
    }
}

// ---------------- host driver ----------------
extern "C" void kernel_launch(void* const* d_in, const int* in_sizes, int n_in,
                              void* d_out, int out_size) {
    (void)in_sizes; (void)n_in; (void)out_size;
    const float* feats = (const float*)d_in[0];
    const int*   labels= (const int*)  d_in[1];
    const float* Ic_w  = (const float*)d_in[2];
    const float* Ic_b  = (const float*)d_in[3];
    const float* Hc_w  = (const float*)d_in[4];
    const float* Hc_b  = (const float*)d_in[5];
    const float* Wq    = (const float*)d_in[6];
    const float* bq    = (const float*)d_in[7];
    const float* Wk    = (const float*)d_in[8];
    const float* bk    = (const float*)d_in[9];
    const float* va    = (const float*)d_in[10];
    const float* W_ih  = (const float*)d_in[11];
    const float* b_ih  = (const float*)d_in[12];
    const float* W_hh  = (const float*)d_in[13];
    const float* b_hh  = (const float*)d_in[14];
    const float* Wout  = (const float*)d_in[15];
    const float* bout  = (const float*)d_in[16];
    float* out = (float*)d_out;

    __half *p_feats16, *p_keys16, *p_Icw16, *p_Wcomb16;
    cudaGetSymbolAddress((void**)&p_feats16, g_feats16);
    cudaGetSymbolAddress((void**)&p_keys16,  g_keys16);
    cudaGetSymbolAddress((void**)&p_Icw16,   g_Icw16);
    cudaGetSymbolAddress((void**)&p_Wcomb16, g_Wcomb16);

    cudaFuncSetAttribute(persist, cudaFuncAttributeMaxDynamicSharedMemorySize, SMEM_DYN);

    // launch 1: all elementwise prep fused
    k_prep_all<<<(B_*S_*C_)/256, 256>>>(feats, Ic_w, Wk, Wout, W_ih, W_hh,
                                        b_ih, b_hh, Wq, bq, Hc_b);
    // launch 2: Wcomb = Wq @ Hc_w  (NN, fp32 in, fp16 out)
    gemm_wcomb_nn<<<dim3(H_/64, A_/64), 256>>>(Wq, Hc_w, p_Wcomb16);
    // launch 3: keys16 = feats @ Ic_w^T + Ic_b
    mma_pre<<<dim3(A_/64, (B_*S_)/64), 256>>>(p_feats16, p_Icw16, Ic_b, p_keys16, C_, A_);
    // launch 4: persistent decode (prologue computes kproj, then 128 steps)
    persist<<<NBLK, 1024, SMEM_DYN>>>(labels, va, bk, bout, out);
}